// round 3
// baseline (speedup 1.0000x reference)
#include <cuda_runtime.h>
#include <math_constants.h>
#include <cstdint>

#define B_ 4
#define N_ 20000
#define F_ 256
#define H_ 8
#define D_ 32
#define E_ 320000
#define M_ (B_ * N_)   // 80000 rows in flattened GEMM

// ---------------------------------------------------------------------------
// Scratch (static __device__ arrays; no allocations allowed)
// ---------------------------------------------------------------------------
__device__ float    g_hprime[(size_t)M_ * F_];      // [B,N,H,D] = [M,256]  ~82MB
__device__ float    g_asrc[(size_t)M_ * H_];        // [B,N,H]
__device__ float    g_atrg[(size_t)M_ * H_];        // [B,N,H]
__device__ int      g_counts[M_];                   // per (b,n) in-degree
__device__ int      g_offsets[M_];                  // exclusive scan per batch
__device__ int      g_cursor[M_];                   // fill cursors
__device__ int      g_sorted_src[(size_t)B_ * E_];  // CSR payload: src per slot
__device__ float    g_w[(size_t)B_ * E_ * H_];      // per-edge per-head weight (CSR order)

// ---------------------------------------------------------------------------
// helpers
// ---------------------------------------------------------------------------
__device__ __forceinline__ float to_tf32(float x) {
    uint32_t u;
    asm("cvt.rna.tf32.f32 %0, %1;" : "=r"(u) : "f"(x));
    return __uint_as_float(u);
}

__device__ __forceinline__ void mma_tf32(float c[4], uint32_t a0, uint32_t a1,
                                         uint32_t a2, uint32_t a3,
                                         uint32_t b0, uint32_t b1) {
    asm volatile(
        "mma.sync.aligned.m16n8k8.row.col.f32.tf32.tf32.f32 "
        "{%0,%1,%2,%3},{%4,%5,%6,%7},{%8,%9},{%0,%1,%2,%3};"
        : "+f"(c[0]), "+f"(c[1]), "+f"(c[2]), "+f"(c[3])
        : "r"(a0), "r"(a1), "r"(a2), "r"(a3), "r"(b0), "r"(b1));
}

__device__ __forceinline__ float leaky_exp(float x) {
    x = x > 0.f ? x : 0.2f * x;
    return __expf(x);
}

// ---------------------------------------------------------------------------
// 0) init: zero counters
// ---------------------------------------------------------------------------
__global__ void init_kernel() {
    int i = blockIdx.x * blockDim.x + threadIdx.x;
    if (i < M_) { g_counts[i] = 0; g_cursor[i] = 0; }
}

// ---------------------------------------------------------------------------
// 1) tf32 GEMM: g_hprime[M,256] = A[M,256] @ W[256,256]^T, fused a_src/a_trg
//    128x128x16 tile, 256 threads = 8 warps in 2(M) x 4(N); warp tile 64x32.
//    Each warp covers exactly one head (32 cols) -> projection in epilogue.
// ---------------------------------------------------------------------------
#define BK_ 16
__global__ __launch_bounds__(256) void gemm_tf32_kernel(const float* __restrict__ A,
                                                        const float* __restrict__ W,
                                                        const float* __restrict__ attn_src,
                                                        const float* __restrict__ attn_trg) {
    __shared__ float As[128][BK_ + 1];
    __shared__ float Bs[128][BK_ + 1];

    const int tid   = threadIdx.x;
    const int lane  = tid & 31;
    const int wid   = tid >> 5;
    const int warpM = wid >> 2;   // 0..1
    const int warpN = wid & 3;    // 0..3
    const int bm    = blockIdx.x * 128;
    const int bn    = blockIdx.y * 128;

    const int lr = tid >> 2;        // 0..63
    const int lc = (tid & 3) * 4;   // 0,4,8,12

    float c[4][4][4];
#pragma unroll
    for (int i = 0; i < 4; i++)
#pragma unroll
        for (int j = 0; j < 4; j++)
#pragma unroll
            for (int q = 0; q < 4; q++) c[i][j][q] = 0.f;

    // preload k0 = 0
    float4 av0 = *(const float4*)(A + (size_t)(bm + lr) * 256 + lc);
    float4 av1 = *(const float4*)(A + (size_t)(bm + lr + 64) * 256 + lc);
    float4 bv0 = *(const float4*)(W + (size_t)(bn + lr) * 256 + lc);
    float4 bv1 = *(const float4*)(W + (size_t)(bn + lr + 64) * 256 + lc);

    const int r = lane >> 2;   // 0..7
    const int q = lane & 3;    // 0..3

    for (int k0 = 0; k0 < 256; k0 += BK_) {
        // store current tile (tf32-rounded)
        As[lr][lc + 0] = to_tf32(av0.x); As[lr][lc + 1] = to_tf32(av0.y);
        As[lr][lc + 2] = to_tf32(av0.z); As[lr][lc + 3] = to_tf32(av0.w);
        As[lr + 64][lc + 0] = to_tf32(av1.x); As[lr + 64][lc + 1] = to_tf32(av1.y);
        As[lr + 64][lc + 2] = to_tf32(av1.z); As[lr + 64][lc + 3] = to_tf32(av1.w);
        Bs[lr][lc + 0] = to_tf32(bv0.x); Bs[lr][lc + 1] = to_tf32(bv0.y);
        Bs[lr][lc + 2] = to_tf32(bv0.z); Bs[lr][lc + 3] = to_tf32(bv0.w);
        Bs[lr + 64][lc + 0] = to_tf32(bv1.x); Bs[lr + 64][lc + 1] = to_tf32(bv1.y);
        Bs[lr + 64][lc + 2] = to_tf32(bv1.z); Bs[lr + 64][lc + 3] = to_tf32(bv1.w);
        __syncthreads();

        if (k0 + BK_ < 256) {   // prefetch next tile (overlaps compute)
            av0 = *(const float4*)(A + (size_t)(bm + lr) * 256 + k0 + BK_ + lc);
            av1 = *(const float4*)(A + (size_t)(bm + lr + 64) * 256 + k0 + BK_ + lc);
            bv0 = *(const float4*)(W + (size_t)(bn + lr) * 256 + k0 + BK_ + lc);
            bv1 = *(const float4*)(W + (size_t)(bn + lr + 64) * 256 + k0 + BK_ + lc);
        }

#pragma unroll
        for (int ks = 0; ks < BK_; ks += 8) {
            uint32_t a[4][4], bf[4][2];
#pragma unroll
            for (int i = 0; i < 4; i++) {
                int row = warpM * 64 + i * 16;
                a[i][0] = __float_as_uint(As[row + r][ks + q]);
                a[i][1] = __float_as_uint(As[row + r + 8][ks + q]);
                a[i][2] = __float_as_uint(As[row + r][ks + q + 4]);
                a[i][3] = __float_as_uint(As[row + r + 8][ks + q + 4]);
            }
#pragma unroll
            for (int j = 0; j < 4; j++) {
                int col = warpN * 32 + j * 8 + r;
                bf[j][0] = __float_as_uint(Bs[col][ks + q]);
                bf[j][1] = __float_as_uint(Bs[col][ks + q + 4]);
            }
#pragma unroll
            for (int i = 0; i < 4; i++)
#pragma unroll
                for (int j = 0; j < 4; j++)
                    mma_tf32(c[i][j], a[i][0], a[i][1], a[i][2], a[i][3],
                             bf[j][0], bf[j][1]);
        }
        __syncthreads();
    }

    // ---- epilogue: store hprime + fused attention projections ----
    const int head = (bn >> 5) + warpN;    // global head index 0..7

    // per-thread column weights: cols j*8 + 2*q + {0,1}
    float ws[8], wt[8];
#pragma unroll
    for (int j = 0; j < 4; j++) {
        int col = head * 32 + j * 8 + 2 * q;
        ws[2 * j + 0] = __ldg(&attn_src[col]);
        ws[2 * j + 1] = __ldg(&attn_src[col + 1]);
        wt[2 * j + 0] = __ldg(&attn_trg[col]);
        wt[2 * j + 1] = __ldg(&attn_trg[col + 1]);
    }

#pragma unroll
    for (int i = 0; i < 4; i++) {
        int m0 = bm + warpM * 64 + i * 16 + r;
        float s0 = 0.f, s1 = 0.f, t0 = 0.f, t1 = 0.f;
#pragma unroll
        for (int j = 0; j < 4; j++) {
            // write hprime
            float* base = g_hprime + (size_t)m0 * 256 + bn + warpN * 32 + j * 8 + 2 * q;
            *(float2*)base = make_float2(c[i][j][0], c[i][j][1]);
            *(float2*)(base + 8 * 256) = make_float2(c[i][j][2], c[i][j][3]);
            // projection partials
            s0 += c[i][j][0] * ws[2 * j] + c[i][j][1] * ws[2 * j + 1];
            s1 += c[i][j][2] * ws[2 * j] + c[i][j][3] * ws[2 * j + 1];
            t0 += c[i][j][0] * wt[2 * j] + c[i][j][1] * wt[2 * j + 1];
            t1 += c[i][j][2] * wt[2 * j] + c[i][j][3] * wt[2 * j + 1];
        }
        // reduce across the 4 lanes sharing the same row (lane & 3 group)
#pragma unroll
        for (int o = 1; o < 4; o <<= 1) {
            s0 += __shfl_xor_sync(0xffffffffu, s0, o);
            s1 += __shfl_xor_sync(0xffffffffu, s1, o);
            t0 += __shfl_xor_sync(0xffffffffu, t0, o);
            t1 += __shfl_xor_sync(0xffffffffu, t1, o);
        }
        if (q == 0) {
            g_asrc[(size_t)m0 * H_ + head]       = s0;
            g_asrc[(size_t)(m0 + 8) * H_ + head] = s1;
            g_atrg[(size_t)m0 * H_ + head]       = t0;
            g_atrg[(size_t)(m0 + 8) * H_ + head] = t1;
        }
    }
}

// ---------------------------------------------------------------------------
// 2) pure histogram of targets (coalesced)
// ---------------------------------------------------------------------------
__global__ __launch_bounds__(256) void hist_kernel(const int* __restrict__ ei) {
    int b = blockIdx.y;
    int e = blockIdx.x * 256 + threadIdx.x;
    if (e < E_) {
        int trg = ei[(size_t)b * 2 * E_ + E_ + e];
        atomicAdd(&g_counts[b * N_ + trg], 1);
    }
}

// ---------------------------------------------------------------------------
// 3) exclusive scan of counts per batch (one 1024-thread block per batch)
// ---------------------------------------------------------------------------
__global__ __launch_bounds__(1024) void scan_kernel() {
    const int b   = blockIdx.x;
    const int tid = threadIdx.x;
    const int SEG = 20;
    __shared__ int sums[1024];

    int vals[SEG];
    int base  = tid * SEG;
    int local = 0;
#pragma unroll
    for (int i = 0; i < SEG; i++) {
        int idx = base + i;
        vals[i] = (idx < N_) ? g_counts[b * N_ + idx] : 0;
        local += vals[i];
    }
    sums[tid] = local;
    __syncthreads();
    for (int off = 1; off < 1024; off <<= 1) {
        int v = (tid >= off) ? sums[tid - off] : 0;
        __syncthreads();
        sums[tid] += v;
        __syncthreads();
    }
    int prefix = (tid > 0) ? sums[tid - 1] : 0;
#pragma unroll
    for (int i = 0; i < SEG; i++) {
        int idx = base + i;
        if (idx < N_) {
            g_offsets[b * N_ + idx] = prefix;
            prefix += vals[i];
        }
    }
}

// ---------------------------------------------------------------------------
// 4) fill CSR buckets: src index + precomputed per-head softmax numerators
//    (global max dropped: exp(e)/sum(exp(e)) is identical; e is bounded ~12)
// ---------------------------------------------------------------------------
__global__ __launch_bounds__(256) void fill_kernel(const int* __restrict__ ei) {
    int b = blockIdx.y;
    int e = blockIdx.x * 256 + threadIdx.x;
    if (e >= E_) return;
    int src = ei[(size_t)b * 2 * E_ + e];
    int trg = ei[(size_t)b * 2 * E_ + E_ + e];
    int pos = g_offsets[b * N_ + trg] + atomicAdd(&g_cursor[b * N_ + trg], 1);
    g_sorted_src[(size_t)b * E_ + pos] = src;

    const float4* as = (const float4*)(g_asrc + (size_t)(b * N_ + src) * H_);
    const float4* at = (const float4*)(g_atrg + (size_t)(b * N_ + trg) * H_);
    float4 s0 = as[0], s1 = as[1];
    float4 t0 = at[0], t1 = at[1];

    float4* wp = (float4*)(g_w + ((size_t)b * E_ + pos) * H_);
    wp[0] = make_float4(leaky_exp(s0.x + t0.x), leaky_exp(s0.y + t0.y),
                        leaky_exp(s0.z + t0.z), leaky_exp(s0.w + t0.w));
    wp[1] = make_float4(leaky_exp(s1.x + t1.x), leaky_exp(s1.y + t1.y),
                        leaky_exp(s1.z + t1.z), leaky_exp(s1.w + t1.w));
}

// ---------------------------------------------------------------------------
// 5) gather-aggregate: block per (n, b); warp h, lane d. Unroll 4 for MLP.
// ---------------------------------------------------------------------------
__global__ __launch_bounds__(256) void aggregate_kernel(float* __restrict__ out) {
    const int n    = blockIdx.x;
    const int b    = blockIdx.y;
    const int h    = threadIdx.x >> 5;
    const int lane = threadIdx.x & 31;

    const int off = g_offsets[b * N_ + n];
    const int deg = g_counts[b * N_ + n];

    const int*   srcs = g_sorted_src + (size_t)b * E_ + off;
    const float* wp   = g_w + ((size_t)b * E_ + off) * H_ + h;
    const float* hpb  = g_hprime + (size_t)b * N_ * 256 + h * 32 + lane;

    float acc = 0.f, den = 0.f;
    int j = 0;
    for (; j + 4 <= deg; j += 4) {
        int s0 = __ldg(srcs + j + 0);
        int s1 = __ldg(srcs + j + 1);
        int s2 = __ldg(srcs + j + 2);
        int s3 = __ldg(srcs + j + 3);
        float w0 = __ldg(wp + (size_t)(j + 0) * H_);
        float w1 = __ldg(wp + (size_t)(j + 1) * H_);
        float w2 = __ldg(wp + (size_t)(j + 2) * H_);
        float w3 = __ldg(wp + (size_t)(j + 3) * H_);
        float v0 = __ldg(hpb + (size_t)s0 * 256);
        float v1 = __ldg(hpb + (size_t)s1 * 256);
        float v2 = __ldg(hpb + (size_t)s2 * 256);
        float v3 = __ldg(hpb + (size_t)s3 * 256);
        den += (w0 + w1) + (w2 + w3);
        acc = fmaf(w0, v0, acc);
        acc = fmaf(w1, v1, acc);
        acc = fmaf(w2, v2, acc);
        acc = fmaf(w3, v3, acc);
    }
    for (; j < deg; j++) {
        int   s = __ldg(srcs + j);
        float w = __ldg(wp + (size_t)j * H_);
        den += w;
        acc = fmaf(w, __ldg(hpb + (size_t)s * 256), acc);
    }
    out[(((size_t)b * H_ + h) * N_ + n) * D_ + lane] = acc / (den + 1e-16f);
}

// ---------------------------------------------------------------------------
// kernel_launch
// ---------------------------------------------------------------------------
extern "C" void kernel_launch(void* const* d_in, const int* in_sizes, int n_in,
                              void* d_out, int out_size) {
    const float* h        = (const float*)d_in[0];
    const int*   ei       = (const int*)d_in[1];
    const float* W        = (const float*)d_in[2];
    const float* attn_src = (const float*)d_in[3];
    const float* attn_trg = (const float*)d_in[4];
    float*       out      = (float*)d_out;

    init_kernel<<<(M_ + 255) / 256, 256>>>();

    dim3 ggrid(M_ / 128, 256 / 128);              // 625 x 2
    gemm_tf32_kernel<<<ggrid, 256>>>(h, W, attn_src, attn_trg);

    dim3 egrid((E_ + 255) / 256, B_);             // 1250 x 4
    hist_kernel<<<egrid, 256>>>(ei);

    scan_kernel<<<B_, 1024>>>();

    fill_kernel<<<egrid, 256>>>(ei);

    dim3 agrid(N_, B_);                           // 20000 x 4
    aggregate_kernel<<<agrid, 256>>>(out);
}

// round 6
// speedup vs baseline: 1.3175x; 1.3175x over previous
#include <cuda_runtime.h>
#include <cuda_fp16.h>
#include <math_constants.h>
#include <cstdint>

#define B_ 4
#define N_ 20000
#define F_ 256
#define H_ 8
#define D_ 32
#define E_ 320000
#define M_ (B_ * N_)   // 80000 rows in flattened GEMM

// ---------------------------------------------------------------------------
// Scratch
// ---------------------------------------------------------------------------
__device__ __half   g_hp16[(size_t)M_ * F_];        // [B,N,H,D] fp16 (~41MB)
__device__ float    g_asrc[(size_t)M_ * H_];        // [B,N,H]
__device__ float    g_atrg[(size_t)M_ * H_];        // [B,N,H]
__device__ int      g_counts[M_];                   // per (b,n) in-degree
__device__ int      g_offsets[M_];                  // exclusive scan per batch
__device__ int      g_cursor[M_];                   // fill cursors
__device__ int      g_sorted_src[(size_t)B_ * E_];  // CSR payload: src per slot
__device__ int      g_segsum[64];                   // scan phase partials

#define SCAN_SEGS 10
#define SCAN_SEG_LEN 2000
#define SCAN_PER_THR 8

// ---------------------------------------------------------------------------
// helpers
// ---------------------------------------------------------------------------
__device__ __forceinline__ float to_tf32(float x) {
    uint32_t u;
    asm("cvt.rna.tf32.f32 %0, %1;" : "=r"(u) : "f"(x));
    return __uint_as_float(u);
}

__device__ __forceinline__ void mma_tf32(float c[4], uint32_t a0, uint32_t a1,
                                         uint32_t a2, uint32_t a3,
                                         uint32_t b0, uint32_t b1) {
    asm volatile(
        "mma.sync.aligned.m16n8k8.row.col.f32.tf32.tf32.f32 "
        "{%0,%1,%2,%3},{%4,%5,%6,%7},{%8,%9},{%0,%1,%2,%3};"
        : "+f"(c[0]), "+f"(c[1]), "+f"(c[2]), "+f"(c[3])
        : "r"(a0), "r"(a1), "r"(a2), "r"(a3), "r"(b0), "r"(b1));
}

__device__ __forceinline__ float leaky_exp(float x) {
    x = x > 0.f ? x : 0.2f * x;
    return __expf(x);
}

// ---------------------------------------------------------------------------
// 0) init
// ---------------------------------------------------------------------------
__global__ void init_kernel() {
    int i = blockIdx.x * blockDim.x + threadIdx.x;
    if (i < M_) { g_counts[i] = 0; g_cursor[i] = 0; }
}

// ---------------------------------------------------------------------------
// 1) tf32 GEMM: A[M,256] @ W[256,256]^T -> g_hp16 (fp16), fused a_src/a_trg.
// ---------------------------------------------------------------------------
#define BK_ 16
__global__ __launch_bounds__(256) void gemm_tf32_kernel(const float* __restrict__ A,
                                                        const float* __restrict__ W,
                                                        const float* __restrict__ attn_src,
                                                        const float* __restrict__ attn_trg) {
    __shared__ float As[128][BK_ + 1];
    __shared__ float Bs[128][BK_ + 1];

    const int tid   = threadIdx.x;
    const int lane  = tid & 31;
    const int wid   = tid >> 5;
    const int warpM = wid >> 2;
    const int warpN = wid & 3;
    const int bm    = blockIdx.x * 128;
    const int bn    = blockIdx.y * 128;

    const int lr = tid >> 2;
    const int lc = (tid & 3) * 4;

    float c[4][4][4];
#pragma unroll
    for (int i = 0; i < 4; i++)
#pragma unroll
        for (int j = 0; j < 4; j++)
#pragma unroll
            for (int q = 0; q < 4; q++) c[i][j][q] = 0.f;

    float4 av0 = *(const float4*)(A + (size_t)(bm + lr) * 256 + lc);
    float4 av1 = *(const float4*)(A + (size_t)(bm + lr + 64) * 256 + lc);
    float4 bv0 = *(const float4*)(W + (size_t)(bn + lr) * 256 + lc);
    float4 bv1 = *(const float4*)(W + (size_t)(bn + lr + 64) * 256 + lc);

    const int r = lane >> 2;
    const int q = lane & 3;

    for (int k0 = 0; k0 < 256; k0 += BK_) {
        As[lr][lc + 0] = to_tf32(av0.x); As[lr][lc + 1] = to_tf32(av0.y);
        As[lr][lc + 2] = to_tf32(av0.z); As[lr][lc + 3] = to_tf32(av0.w);
        As[lr + 64][lc + 0] = to_tf32(av1.x); As[lr + 64][lc + 1] = to_tf32(av1.y);
        As[lr + 64][lc + 2] = to_tf32(av1.z); As[lr + 64][lc + 3] = to_tf32(av1.w);
        Bs[lr][lc + 0] = to_tf32(bv0.x); Bs[lr][lc + 1] = to_tf32(bv0.y);
        Bs[lr][lc + 2] = to_tf32(bv0.z); Bs[lr][lc + 3] = to_tf32(bv0.w);
        Bs[lr + 64][lc + 0] = to_tf32(bv1.x); Bs[lr + 64][lc + 1] = to_tf32(bv1.y);
        Bs[lr + 64][lc + 2] = to_tf32(bv1.z); Bs[lr + 64][lc + 3] = to_tf32(bv1.w);
        __syncthreads();

        if (k0 + BK_ < 256) {
            av0 = *(const float4*)(A + (size_t)(bm + lr) * 256 + k0 + BK_ + lc);
            av1 = *(const float4*)(A + (size_t)(bm + lr + 64) * 256 + k0 + BK_ + lc);
            bv0 = *(const float4*)(W + (size_t)(bn + lr) * 256 + k0 + BK_ + lc);
            bv1 = *(const float4*)(W + (size_t)(bn + lr + 64) * 256 + k0 + BK_ + lc);
        }

#pragma unroll
        for (int ks = 0; ks < BK_; ks += 8) {
            uint32_t a[4][4], bf[4][2];
#pragma unroll
            for (int i = 0; i < 4; i++) {
                int row = warpM * 64 + i * 16;
                a[i][0] = __float_as_uint(As[row + r][ks + q]);
                a[i][1] = __float_as_uint(As[row + r + 8][ks + q]);
                a[i][2] = __float_as_uint(As[row + r][ks + q + 4]);
                a[i][3] = __float_as_uint(As[row + r + 8][ks + q + 4]);
            }
#pragma unroll
            for (int j = 0; j < 4; j++) {
                int col = warpN * 32 + j * 8 + r;
                bf[j][0] = __float_as_uint(Bs[col][ks + q]);
                bf[j][1] = __float_as_uint(Bs[col][ks + q + 4]);
            }
#pragma unroll
            for (int i = 0; i < 4; i++)
#pragma unroll
                for (int j = 0; j < 4; j++)
                    mma_tf32(c[i][j], a[i][0], a[i][1], a[i][2], a[i][3],
                             bf[j][0], bf[j][1]);
        }
        __syncthreads();
    }

    const int head = (bn >> 5) + warpN;

    float ws[8], wt[8];
#pragma unroll
    for (int j = 0; j < 4; j++) {
        int col = head * 32 + j * 8 + 2 * q;
        ws[2 * j + 0] = __ldg(&attn_src[col]);
        ws[2 * j + 1] = __ldg(&attn_src[col + 1]);
        wt[2 * j + 0] = __ldg(&attn_trg[col]);
        wt[2 * j + 1] = __ldg(&attn_trg[col + 1]);
    }

#pragma unroll
    for (int i = 0; i < 4; i++) {
        int m0 = bm + warpM * 64 + i * 16 + r;
        float s0 = 0.f, s1 = 0.f, t0 = 0.f, t1 = 0.f;
#pragma unroll
        for (int j = 0; j < 4; j++) {
            __half* base = g_hp16 + (size_t)m0 * 256 + bn + warpN * 32 + j * 8 + 2 * q;
            *(__half2*)base = __floats2half2_rn(c[i][j][0], c[i][j][1]);
            *(__half2*)(base + 8 * 256) = __floats2half2_rn(c[i][j][2], c[i][j][3]);
            s0 += c[i][j][0] * ws[2 * j] + c[i][j][1] * ws[2 * j + 1];
            s1 += c[i][j][2] * ws[2 * j] + c[i][j][3] * ws[2 * j + 1];
            t0 += c[i][j][0] * wt[2 * j] + c[i][j][1] * wt[2 * j + 1];
            t1 += c[i][j][2] * wt[2 * j] + c[i][j][3] * wt[2 * j + 1];
        }
#pragma unroll
        for (int o = 1; o < 4; o <<= 1) {
            s0 += __shfl_xor_sync(0xffffffffu, s0, o);
            s1 += __shfl_xor_sync(0xffffffffu, s1, o);
            t0 += __shfl_xor_sync(0xffffffffu, t0, o);
            t1 += __shfl_xor_sync(0xffffffffu, t1, o);
        }
        if (q == 0) {
            g_asrc[(size_t)m0 * H_ + head]       = s0;
            g_asrc[(size_t)(m0 + 8) * H_ + head] = s1;
            g_atrg[(size_t)m0 * H_ + head]       = t0;
            g_atrg[(size_t)(m0 + 8) * H_ + head] = t1;
        }
    }
}

// ---------------------------------------------------------------------------
// 2) histogram of targets
// ---------------------------------------------------------------------------
__global__ __launch_bounds__(256) void hist_kernel(const int* __restrict__ ei) {
    int b = blockIdx.y;
    int e = blockIdx.x * 256 + threadIdx.x;
    if (e < E_) {
        int trg = ei[(size_t)b * 2 * E_ + E_ + e];
        atomicAdd(&g_counts[b * N_ + trg], 1);
    }
}

// ---------------------------------------------------------------------------
// 3) scan, 3-phase
// ---------------------------------------------------------------------------
__global__ __launch_bounds__(256) void scan1_kernel() {
    const int seg  = blockIdx.x;
    const int base = seg * SCAN_SEG_LEN;
    int local = 0;
    for (int i = threadIdx.x; i < SCAN_SEG_LEN; i += 256)
        local += g_counts[base + i];
#pragma unroll
    for (int o = 16; o > 0; o >>= 1) local += __shfl_xor_sync(0xffffffffu, local, o);
    __shared__ int warpsum[8];
    if ((threadIdx.x & 31) == 0) warpsum[threadIdx.x >> 5] = local;
    __syncthreads();
    if (threadIdx.x == 0) {
        int s = 0;
#pragma unroll
        for (int w = 0; w < 8; w++) s += warpsum[w];
        g_segsum[seg] = s;
    }
}

__global__ void scan2_kernel() {
    if (threadIdx.x == 0) {
#pragma unroll
        for (int b = 0; b < B_; b++) {
            int run = 0;
            for (int s = 0; s < SCAN_SEGS; s++) {
                int v = g_segsum[b * SCAN_SEGS + s];
                g_segsum[b * SCAN_SEGS + s] = run;
                run += v;
            }
        }
    }
}

__global__ __launch_bounds__(256) void scan3_kernel() {
    const int seg  = blockIdx.x;
    const int base = seg * SCAN_SEG_LEN;
    const int tid  = threadIdx.x;
    __shared__ int sums[256];

    int vals[SCAN_PER_THR];
    int tb = tid * SCAN_PER_THR;
    int local = 0;
#pragma unroll
    for (int i = 0; i < SCAN_PER_THR; i++) {
        int idx = tb + i;
        vals[i] = (idx < SCAN_SEG_LEN) ? g_counts[base + idx] : 0;
        local += vals[i];
    }
    int v = local;
    int lane = tid & 31, w = tid >> 5;
#pragma unroll
    for (int o = 1; o < 32; o <<= 1) {
        int u = __shfl_up_sync(0xffffffffu, v, o);
        if (lane >= o) v += u;
    }
    __shared__ int wsum[8];
    if (lane == 31) wsum[w] = v;
    __syncthreads();
    if (tid < 8) {
        int u = wsum[tid];
#pragma unroll
        for (int o = 1; o < 8; o <<= 1) {
            int p = __shfl_up_sync(0xffu, u, o);
            if (tid >= o) u += p;
        }
        sums[tid] = u;
    }
    __syncthreads();
    int prefix = v - local + (w > 0 ? sums[w - 1] : 0) + g_segsum[seg];
#pragma unroll
    for (int i = 0; i < SCAN_PER_THR; i++) {
        int idx = tb + i;
        if (idx < SCAN_SEG_LEN) {
            g_offsets[base + idx] = prefix;
            prefix += vals[i];
        }
    }
}

// ---------------------------------------------------------------------------
// 4) fill CSR buckets (src only)
// ---------------------------------------------------------------------------
__global__ __launch_bounds__(256) void fill_kernel(const int* __restrict__ ei) {
    int b = blockIdx.y;
    int e = blockIdx.x * 256 + threadIdx.x;
    if (e >= E_) return;
    int src = ei[(size_t)b * 2 * E_ + e];
    int trg = ei[(size_t)b * 2 * E_ + E_ + e];
    int pos = g_offsets[b * N_ + trg] + atomicAdd(&g_cursor[b * N_ + trg], 1);
    g_sorted_src[(size_t)b * E_ + pos] = src;
}

// ---------------------------------------------------------------------------
// 5) warp-synchronous gather-aggregate. One warp per (node, head-pair hp).
//    Lanes 0..15 -> head 2hp (d = 2*lane, 2*lane+1)
//    Lanes 16..31 -> head 2hp+1 (d = 2*(lane-16), ...)
//    No smem, no __syncthreads. Weights computed in registers, shfl-broadcast.
// ---------------------------------------------------------------------------
__global__ __launch_bounds__(256) void aggregate_kernel(float* __restrict__ out) {
    const int tid  = threadIdx.x;
    const int wid  = tid >> 5;
    const int lane = tid & 31;
    const int n    = blockIdx.x * 2 + (wid >> 2);   // 2 nodes per block
    const int b    = blockIdx.y;
    const int hp   = wid & 3;                       // head pair 0..3

    const int off = g_offsets[b * N_ + n];
    const int deg = g_counts[b * N_ + n];

    // a_trg for this node's head pair (broadcast load, L1-cached)
    const float2 at = *(const float2*)(g_atrg + (size_t)(b * N_ + n) * H_ + 2 * hp);

    const int*    srcs = g_sorted_src + (size_t)b * E_ + off;
    const float*  asb  = g_asrc + (size_t)b * N_ * H_ + 2 * hp;
    const __half2* hpb = (const __half2*)g_hp16 + (size_t)b * N_ * 128 + hp * 32 + lane;

    float2 acc = make_float2(0.f, 0.f);
    float  den = 0.f;
    const bool low = lane < 16;

    for (int c0 = 0; c0 < deg; c0 += 32) {
        const int cnt = min(32, deg - c0);
        // phase 1: lanes < cnt prepare (src, w0, w1)
        int   src_r = 0;
        float w0_r = 0.f, w1_r = 0.f;
        if (lane < cnt) {
            src_r = __ldg(srcs + c0 + lane);
            float2 a = __ldg((const float2*)(asb + (size_t)src_r * H_));
            w0_r = leaky_exp(a.x + at.x);
            w1_r = leaky_exp(a.y + at.y);
        }
        // phase 2: broadcast + gather, unroll 4 for MLP
        int j = 0;
        for (; j + 4 <= cnt; j += 4) {
            int s0 = __shfl_sync(0xffffffffu, src_r, j + 0);
            int s1 = __shfl_sync(0xffffffffu, src_r, j + 1);
            int s2 = __shfl_sync(0xffffffffu, src_r, j + 2);
            int s3 = __shfl_sync(0xffffffffu, src_r, j + 3);
            float wa0 = __shfl_sync(0xffffffffu, w0_r, j + 0);
            float wb0 = __shfl_sync(0xffffffffu, w1_r, j + 0);
            float wa1 = __shfl_sync(0xffffffffu, w0_r, j + 1);
            float wb1 = __shfl_sync(0xffffffffu, w1_r, j + 1);
            float wa2 = __shfl_sync(0xffffffffu, w0_r, j + 2);
            float wb2 = __shfl_sync(0xffffffffu, w1_r, j + 2);
            float wa3 = __shfl_sync(0xffffffffu, w0_r, j + 3);
            float wb3 = __shfl_sync(0xffffffffu, w1_r, j + 3);
            __half2 h0 = __ldg(hpb + (size_t)s0 * 128);
            __half2 h1 = __ldg(hpb + (size_t)s1 * 128);
            __half2 h2 = __ldg(hpb + (size_t)s2 * 128);
            __half2 h3 = __ldg(hpb + (size_t)s3 * 128);
            float m0 = low ? wa0 : wb0;
            float m1 = low ? wa1 : wb1;
            float m2 = low ? wa2 : wb2;
            float m3 = low ? wa3 : wb3;
            den += (m0 + m1) + (m2 + m3);
            float2 v0 = __half22float2(h0);
            float2 v1 = __half22float2(h1);
            float2 v2 = __half22float2(h2);
            float2 v3 = __half22float2(h3);
            acc.x = fmaf(m0, v0.x, acc.x); acc.y = fmaf(m0, v0.y, acc.y);
            acc.x = fmaf(m1, v1.x, acc.x); acc.y = fmaf(m1, v1.y, acc.y);
            acc.x = fmaf(m2, v2.x, acc.x); acc.y = fmaf(m2, v2.y, acc.y);
            acc.x = fmaf(m3, v3.x, acc.x); acc.y = fmaf(m3, v3.y, acc.y);
        }
        for (; j < cnt; j++) {
            int   s  = __shfl_sync(0xffffffffu, src_r, j);
            float wa = __shfl_sync(0xffffffffu, w0_r, j);
            float wb = __shfl_sync(0xffffffffu, w1_r, j);
            float m  = low ? wa : wb;
            float2 v = __half22float2(__ldg(hpb + (size_t)s * 128));
            den += m;
            acc.x = fmaf(m, v.x, acc.x);
            acc.y = fmaf(m, v.y, acc.y);
        }
    }

    const float inv = 1.f / (den + 1e-16f);
    const int head = 2 * hp + (low ? 0 : 1);
    const int d0   = 2 * (low ? lane : lane - 16);
    float2* op = (float2*)(out + (((size_t)b * H_ + head) * N_ + n) * D_ + d0);
    *op = make_float2(acc.x * inv, acc.y * inv);
}

// ---------------------------------------------------------------------------
// kernel_launch — fork edge-prep onto a side stream, overlap with GEMM.
// Streams/events created once on the first (uncaptured correctness) call;
// every call enqueues identical work.
// ---------------------------------------------------------------------------
extern "C" void kernel_launch(void* const* d_in, const int* in_sizes, int n_in,
                              void* d_out, int out_size) {
    const float* h        = (const float*)d_in[0];
    const int*   ei       = (const int*)d_in[1];
    const float* W        = (const float*)d_in[2];
    const float* attn_src = (const float*)d_in[3];
    const float* attn_trg = (const float*)d_in[4];
    float*       out      = (float*)d_out;

    static cudaStream_t s_side = nullptr;
    static cudaEvent_t  ev_fork = nullptr, ev_join = nullptr;
    if (s_side == nullptr) {
        cudaStreamCreateWithFlags(&s_side, cudaStreamNonBlocking);
        cudaEventCreateWithFlags(&ev_fork, cudaEventDisableTiming);
        cudaEventCreateWithFlags(&ev_join, cudaEventDisableTiming);
    }

    // fork
    cudaEventRecord(ev_fork, 0);
    cudaStreamWaitEvent(s_side, ev_fork, 0);

    // side stream: edge prep (independent of GEMM)
    dim3 egrid((E_ + 255) / 256, B_);
    init_kernel<<<(M_ + 255) / 256, 256, 0, s_side>>>();
    hist_kernel<<<egrid, 256, 0, s_side>>>(ei);
    scan1_kernel<<<B_ * SCAN_SEGS, 256, 0, s_side>>>();
    scan2_kernel<<<1, 32, 0, s_side>>>();
    scan3_kernel<<<B_ * SCAN_SEGS, 256, 0, s_side>>>();
    fill_kernel<<<egrid, 256, 0, s_side>>>(ei);
    cudaEventRecord(ev_join, s_side);

    // main stream: GEMM (+ fused projections)
    dim3 ggrid(M_ / 128, 256 / 128);
    gemm_tf32_kernel<<<ggrid, 256>>>(h, W, attn_src, attn_trg);

    // join, then aggregate
    cudaStreamWaitEvent(0, ev_join, 0);
    dim3 agrid(N_ / 2, B_);                       // 2 nodes per block
    aggregate_kernel<<<agrid, 256>>>(out);
}

// round 7
// speedup vs baseline: 1.5262x; 1.1584x over previous
#include <cuda_runtime.h>
#include <cuda_fp16.h>
#include <math_constants.h>
#include <cstdint>

#define B_ 4
#define N_ 20000
#define F_ 256
#define H_ 8
#define D_ 32
#define E_ 320000
#define M_ (B_ * N_)   // 80000 rows in flattened GEMM

// ---------------------------------------------------------------------------
// Scratch
// ---------------------------------------------------------------------------
__device__ __half   g_hp16[(size_t)M_ * F_];        // [B,N,H,D] fp16 (~41MB)
__device__ float    g_asrc[(size_t)M_ * H_];        // [B,N,H]
__device__ float    g_atrg[(size_t)M_ * H_];        // [B,N,H]
__device__ int      g_counts[M_];                   // per (b,n) in-degree
__device__ int      g_offsets[M_];                  // exclusive scan per batch
__device__ int      g_cursor[M_];                   // fill cursors
__device__ int      g_sorted_src[(size_t)B_ * E_];  // CSR payload: src per slot
__device__ int      g_segsum[64];                   // scan phase partials

#define SCAN_SEGS 10
#define SCAN_SEG_LEN 2000
#define SCAN_PER_THR 8

// ---------------------------------------------------------------------------
// helpers
// ---------------------------------------------------------------------------
__device__ __forceinline__ void mma_fp16(float c[4], uint32_t a0, uint32_t a1,
                                         uint32_t a2, uint32_t a3,
                                         uint32_t b0, uint32_t b1) {
    asm volatile(
        "mma.sync.aligned.m16n8k16.row.col.f32.f16.f16.f32 "
        "{%0,%1,%2,%3},{%4,%5,%6,%7},{%8,%9},{%0,%1,%2,%3};"
        : "+f"(c[0]), "+f"(c[1]), "+f"(c[2]), "+f"(c[3])
        : "r"(a0), "r"(a1), "r"(a2), "r"(a3), "r"(b0), "r"(b1));
}

__device__ __forceinline__ float leaky_exp(float x) {
    x = x > 0.f ? x : 0.2f * x;
    return __expf(x);
}

// ---------------------------------------------------------------------------
// 0) init
// ---------------------------------------------------------------------------
__global__ void init_kernel() {
    int i = blockIdx.x * blockDim.x + threadIdx.x;
    if (i < M_) { g_counts[i] = 0; g_cursor[i] = 0; }
}

// ---------------------------------------------------------------------------
// 1) fp16 GEMM (fp32 accum): A[M,256] @ W[256,256]^T -> g_hp16, fused a_src/a_trg.
//    128x128x16 tile, 8 warps 2(M)x4(N), warp tile 64x32 (one head per warp).
//    fp16 has the same 10-bit mantissa as tf32; fp32 accumulators -> same error.
// ---------------------------------------------------------------------------
#define BK_ 16
#define BKP_ 24   // padded row length in halves (12 words -> conflict-free frags)
__global__ __launch_bounds__(256) void gemm_fp16_kernel(const float* __restrict__ A,
                                                        const float* __restrict__ W,
                                                        const float* __restrict__ attn_src,
                                                        const float* __restrict__ attn_trg) {
    __shared__ __half As[128][BKP_];
    __shared__ __half Bs[128][BKP_];

    const int tid   = threadIdx.x;
    const int lane  = tid & 31;
    const int wid   = tid >> 5;
    const int warpM = wid >> 2;
    const int warpN = wid & 3;
    const int bm    = blockIdx.x * 128;
    const int bn    = blockIdx.y * 128;

    const int lr = tid >> 2;        // 0..63
    const int lc = (tid & 3) * 4;   // 0,4,8,12

    float c[4][4][4];
#pragma unroll
    for (int i = 0; i < 4; i++)
#pragma unroll
        for (int j = 0; j < 4; j++)
#pragma unroll
            for (int q = 0; q < 4; q++) c[i][j][q] = 0.f;

    float4 av0 = *(const float4*)(A + (size_t)(bm + lr) * 256 + lc);
    float4 av1 = *(const float4*)(A + (size_t)(bm + lr + 64) * 256 + lc);
    float4 bv0 = *(const float4*)(W + (size_t)(bn + lr) * 256 + lc);
    float4 bv1 = *(const float4*)(W + (size_t)(bn + lr + 64) * 256 + lc);

    const int r = lane >> 2;   // 0..7
    const int q = lane & 3;    // 0..3

    for (int k0 = 0; k0 < 256; k0 += BK_) {
        *(__half2*)&As[lr][lc]          = __floats2half2_rn(av0.x, av0.y);
        *(__half2*)&As[lr][lc + 2]      = __floats2half2_rn(av0.z, av0.w);
        *(__half2*)&As[lr + 64][lc]     = __floats2half2_rn(av1.x, av1.y);
        *(__half2*)&As[lr + 64][lc + 2] = __floats2half2_rn(av1.z, av1.w);
        *(__half2*)&Bs[lr][lc]          = __floats2half2_rn(bv0.x, bv0.y);
        *(__half2*)&Bs[lr][lc + 2]      = __floats2half2_rn(bv0.z, bv0.w);
        *(__half2*)&Bs[lr + 64][lc]     = __floats2half2_rn(bv1.x, bv1.y);
        *(__half2*)&Bs[lr + 64][lc + 2] = __floats2half2_rn(bv1.z, bv1.w);
        __syncthreads();

        if (k0 + BK_ < 256) {
            av0 = *(const float4*)(A + (size_t)(bm + lr) * 256 + k0 + BK_ + lc);
            av1 = *(const float4*)(A + (size_t)(bm + lr + 64) * 256 + k0 + BK_ + lc);
            bv0 = *(const float4*)(W + (size_t)(bn + lr) * 256 + k0 + BK_ + lc);
            bv1 = *(const float4*)(W + (size_t)(bn + lr + 64) * 256 + k0 + BK_ + lc);
        }

        // one m16n8k16 step covers the whole BK=16
        uint32_t a[4][4], bf[4][2];
#pragma unroll
        for (int i = 0; i < 4; i++) {
            int row = warpM * 64 + i * 16;
            a[i][0] = *(const uint32_t*)&As[row + r][2 * q];
            a[i][1] = *(const uint32_t*)&As[row + r + 8][2 * q];
            a[i][2] = *(const uint32_t*)&As[row + r][2 * q + 8];
            a[i][3] = *(const uint32_t*)&As[row + r + 8][2 * q + 8];
        }
#pragma unroll
        for (int j = 0; j < 4; j++) {
            int col = warpN * 32 + j * 8 + r;
            bf[j][0] = *(const uint32_t*)&Bs[col][2 * q];
            bf[j][1] = *(const uint32_t*)&Bs[col][2 * q + 8];
        }
#pragma unroll
        for (int i = 0; i < 4; i++)
#pragma unroll
            for (int j = 0; j < 4; j++)
                mma_fp16(c[i][j], a[i][0], a[i][1], a[i][2], a[i][3],
                         bf[j][0], bf[j][1]);
        __syncthreads();
    }

    // ---- epilogue: fp16 hprime store + fused projections ----
    const int head = (bn >> 5) + warpN;

    float ws[8], wt[8];
#pragma unroll
    for (int j = 0; j < 4; j++) {
        int col = head * 32 + j * 8 + 2 * q;
        ws[2 * j + 0] = __ldg(&attn_src[col]);
        ws[2 * j + 1] = __ldg(&attn_src[col + 1]);
        wt[2 * j + 0] = __ldg(&attn_trg[col]);
        wt[2 * j + 1] = __ldg(&attn_trg[col + 1]);
    }

#pragma unroll
    for (int i = 0; i < 4; i++) {
        int m0 = bm + warpM * 64 + i * 16 + r;
        float s0 = 0.f, s1 = 0.f, t0 = 0.f, t1 = 0.f;
#pragma unroll
        for (int j = 0; j < 4; j++) {
            __half* base = g_hp16 + (size_t)m0 * 256 + bn + warpN * 32 + j * 8 + 2 * q;
            *(__half2*)base = __floats2half2_rn(c[i][j][0], c[i][j][1]);
            *(__half2*)(base + 8 * 256) = __floats2half2_rn(c[i][j][2], c[i][j][3]);
            s0 += c[i][j][0] * ws[2 * j] + c[i][j][1] * ws[2 * j + 1];
            s1 += c[i][j][2] * ws[2 * j] + c[i][j][3] * ws[2 * j + 1];
            t0 += c[i][j][0] * wt[2 * j] + c[i][j][1] * wt[2 * j + 1];
            t1 += c[i][j][2] * wt[2 * j] + c[i][j][3] * wt[2 * j + 1];
        }
#pragma unroll
        for (int o = 1; o < 4; o <<= 1) {
            s0 += __shfl_xor_sync(0xffffffffu, s0, o);
            s1 += __shfl_xor_sync(0xffffffffu, s1, o);
            t0 += __shfl_xor_sync(0xffffffffu, t0, o);
            t1 += __shfl_xor_sync(0xffffffffu, t1, o);
        }
        if (q == 0) {
            g_asrc[(size_t)m0 * H_ + head]       = s0;
            g_asrc[(size_t)(m0 + 8) * H_ + head] = s1;
            g_atrg[(size_t)m0 * H_ + head]       = t0;
            g_atrg[(size_t)(m0 + 8) * H_ + head] = t1;
        }
    }
}

// ---------------------------------------------------------------------------
// 2) histogram of targets
// ---------------------------------------------------------------------------
__global__ __launch_bounds__(256) void hist_kernel(const int* __restrict__ ei) {
    int b = blockIdx.y;
    int e = blockIdx.x * 256 + threadIdx.x;
    if (e < E_) {
        int trg = ei[(size_t)b * 2 * E_ + E_ + e];
        atomicAdd(&g_counts[b * N_ + trg], 1);
    }
}

// ---------------------------------------------------------------------------
// 3) scan, 2-phase (scan2 folded into scan3)
// ---------------------------------------------------------------------------
__global__ __launch_bounds__(256) void scan1_kernel() {
    const int seg  = blockIdx.x;
    const int base = seg * SCAN_SEG_LEN;
    int local = 0;
    for (int i = threadIdx.x; i < SCAN_SEG_LEN; i += 256)
        local += g_counts[base + i];
#pragma unroll
    for (int o = 16; o > 0; o >>= 1) local += __shfl_xor_sync(0xffffffffu, local, o);
    __shared__ int warpsum[8];
    if ((threadIdx.x & 31) == 0) warpsum[threadIdx.x >> 5] = local;
    __syncthreads();
    if (threadIdx.x == 0) {
        int s = 0;
#pragma unroll
        for (int w = 0; w < 8; w++) s += warpsum[w];
        g_segsum[seg] = s;
    }
}

__global__ __launch_bounds__(256) void scan3_kernel() {
    const int seg  = blockIdx.x;
    const int base = seg * SCAN_SEG_LEN;
    const int tid  = threadIdx.x;
    __shared__ int sums[256];
    __shared__ int segbase;

    if (tid == 0) {   // inline exclusive prefix over this batch's segments
        int b = seg / SCAN_SEGS;
        int s = 0;
        for (int k = b * SCAN_SEGS; k < seg; k++) s += g_segsum[k];
        segbase = s;
    }

    int vals[SCAN_PER_THR];
    int tb = tid * SCAN_PER_THR;
    int local = 0;
#pragma unroll
    for (int i = 0; i < SCAN_PER_THR; i++) {
        int idx = tb + i;
        vals[i] = (idx < SCAN_SEG_LEN) ? g_counts[base + idx] : 0;
        local += vals[i];
    }
    int v = local;
    int lane = tid & 31, w = tid >> 5;
#pragma unroll
    for (int o = 1; o < 32; o <<= 1) {
        int u = __shfl_up_sync(0xffffffffu, v, o);
        if (lane >= o) v += u;
    }
    __shared__ int wsum[8];
    if (lane == 31) wsum[w] = v;
    __syncthreads();
    if (tid < 8) {
        int u = wsum[tid];
#pragma unroll
        for (int o = 1; o < 8; o <<= 1) {
            int p = __shfl_up_sync(0xffu, u, o);
            if (tid >= o) u += p;
        }
        sums[tid] = u;
    }
    __syncthreads();
    int prefix = v - local + (w > 0 ? sums[w - 1] : 0) + segbase;
#pragma unroll
    for (int i = 0; i < SCAN_PER_THR; i++) {
        int idx = tb + i;
        if (idx < SCAN_SEG_LEN) {
            g_offsets[base + idx] = prefix;
            prefix += vals[i];
        }
    }
}

// ---------------------------------------------------------------------------
// 4) fill CSR buckets (src only)
// ---------------------------------------------------------------------------
__global__ __launch_bounds__(256) void fill_kernel(const int* __restrict__ ei) {
    int b = blockIdx.y;
    int e = blockIdx.x * 256 + threadIdx.x;
    if (e >= E_) return;
    int src = ei[(size_t)b * 2 * E_ + e];
    int trg = ei[(size_t)b * 2 * E_ + E_ + e];
    int pos = g_offsets[b * N_ + trg] + atomicAdd(&g_cursor[b * N_ + trg], 1);
    g_sorted_src[(size_t)b * E_ + pos] = src;
}

// ---------------------------------------------------------------------------
// 5) warp-synchronous gather-aggregate. One warp per (node, head-pair hp).
// ---------------------------------------------------------------------------
__global__ __launch_bounds__(256) void aggregate_kernel(float* __restrict__ out) {
    const int tid  = threadIdx.x;
    const int wid  = tid >> 5;
    const int lane = tid & 31;
    const int n    = blockIdx.x * 2 + (wid >> 2);
    const int b    = blockIdx.y;
    const int hp   = wid & 3;

    const int off = g_offsets[b * N_ + n];
    const int deg = g_counts[b * N_ + n];

    const float2 at = *(const float2*)(g_atrg + (size_t)(b * N_ + n) * H_ + 2 * hp);

    const int*    srcs = g_sorted_src + (size_t)b * E_ + off;
    const float*  asb  = g_asrc + (size_t)b * N_ * H_ + 2 * hp;
    const __half2* hpb = (const __half2*)g_hp16 + (size_t)b * N_ * 128 + hp * 32 + lane;

    float2 acc = make_float2(0.f, 0.f);
    float  den = 0.f;
    const bool low = lane < 16;

    for (int c0 = 0; c0 < deg; c0 += 32) {
        const int cnt = min(32, deg - c0);
        int   src_r = 0;
        float w0_r = 0.f, w1_r = 0.f;
        if (lane < cnt) {
            src_r = __ldg(srcs + c0 + lane);
            float2 a = __ldg((const float2*)(asb + (size_t)src_r * H_));
            w0_r = leaky_exp(a.x + at.x);
            w1_r = leaky_exp(a.y + at.y);
        }
        int j = 0;
        for (; j + 4 <= cnt; j += 4) {
            int s0 = __shfl_sync(0xffffffffu, src_r, j + 0);
            int s1 = __shfl_sync(0xffffffffu, src_r, j + 1);
            int s2 = __shfl_sync(0xffffffffu, src_r, j + 2);
            int s3 = __shfl_sync(0xffffffffu, src_r, j + 3);
            float wa0 = __shfl_sync(0xffffffffu, w0_r, j + 0);
            float wb0 = __shfl_sync(0xffffffffu, w1_r, j + 0);
            float wa1 = __shfl_sync(0xffffffffu, w0_r, j + 1);
            float wb1 = __shfl_sync(0xffffffffu, w1_r, j + 1);
            float wa2 = __shfl_sync(0xffffffffu, w0_r, j + 2);
            float wb2 = __shfl_sync(0xffffffffu, w1_r, j + 2);
            float wa3 = __shfl_sync(0xffffffffu, w0_r, j + 3);
            float wb3 = __shfl_sync(0xffffffffu, w1_r, j + 3);
            __half2 h0 = __ldg(hpb + (size_t)s0 * 128);
            __half2 h1 = __ldg(hpb + (size_t)s1 * 128);
            __half2 h2 = __ldg(hpb + (size_t)s2 * 128);
            __half2 h3 = __ldg(hpb + (size_t)s3 * 128);
            float m0 = low ? wa0 : wb0;
            float m1 = low ? wa1 : wb1;
            float m2 = low ? wa2 : wb2;
            float m3 = low ? wa3 : wb3;
            den += (m0 + m1) + (m2 + m3);
            float2 v0 = __half22float2(h0);
            float2 v1 = __half22float2(h1);
            float2 v2 = __half22float2(h2);
            float2 v3 = __half22float2(h3);
            acc.x = fmaf(m0, v0.x, acc.x); acc.y = fmaf(m0, v0.y, acc.y);
            acc.x = fmaf(m1, v1.x, acc.x); acc.y = fmaf(m1, v1.y, acc.y);
            acc.x = fmaf(m2, v2.x, acc.x); acc.y = fmaf(m2, v2.y, acc.y);
            acc.x = fmaf(m3, v3.x, acc.x); acc.y = fmaf(m3, v3.y, acc.y);
        }
        for (; j < cnt; j++) {
            int   s  = __shfl_sync(0xffffffffu, src_r, j);
            float wa = __shfl_sync(0xffffffffu, w0_r, j);
            float wb = __shfl_sync(0xffffffffu, w1_r, j);
            float m  = low ? wa : wb;
            float2 v = __half22float2(__ldg(hpb + (size_t)s * 128));
            den += m;
            acc.x = fmaf(m, v.x, acc.x);
            acc.y = fmaf(m, v.y, acc.y);
        }
    }

    const float inv = 1.f / (den + 1e-16f);
    const int head = 2 * hp + (low ? 0 : 1);
    const int d0   = 2 * (low ? lane : lane - 16);
    float2* op = (float2*)(out + (((size_t)b * H_ + head) * N_ + n) * D_ + d0);
    *op = make_float2(acc.x * inv, acc.y * inv);
}

// ---------------------------------------------------------------------------
// kernel_launch — fork edge-prep onto a side stream, overlap with GEMM.
// ---------------------------------------------------------------------------
extern "C" void kernel_launch(void* const* d_in, const int* in_sizes, int n_in,
                              void* d_out, int out_size) {
    const float* h        = (const float*)d_in[0];
    const int*   ei       = (const int*)d_in[1];
    const float* W        = (const float*)d_in[2];
    const float* attn_src = (const float*)d_in[3];
    const float* attn_trg = (const float*)d_in[4];
    float*       out      = (float*)d_out;

    static cudaStream_t s_side = nullptr;
    static cudaEvent_t  ev_fork = nullptr, ev_join = nullptr;
    if (s_side == nullptr) {
        cudaStreamCreateWithFlags(&s_side, cudaStreamNonBlocking);
        cudaEventCreateWithFlags(&ev_fork, cudaEventDisableTiming);
        cudaEventCreateWithFlags(&ev_join, cudaEventDisableTiming);
    }

    // fork
    cudaEventRecord(ev_fork, 0);
    cudaStreamWaitEvent(s_side, ev_fork, 0);

    // side stream: edge prep (independent of GEMM)
    dim3 egrid((E_ + 255) / 256, B_);
    init_kernel<<<(M_ + 255) / 256, 256, 0, s_side>>>();
    hist_kernel<<<egrid, 256, 0, s_side>>>(ei);
    scan1_kernel<<<B_ * SCAN_SEGS, 256, 0, s_side>>>();
    scan3_kernel<<<B_ * SCAN_SEGS, 256, 0, s_side>>>();
    fill_kernel<<<egrid, 256, 0, s_side>>>(ei);
    cudaEventRecord(ev_join, s_side);

    // main stream: GEMM (+ fused projections)
    dim3 ggrid(M_ / 128, 256 / 128);
    gemm_fp16_kernel<<<ggrid, 256>>>(h, W, attn_src, attn_trg);

    // join, then aggregate
    cudaStreamWaitEvent(0, ev_join, 0);
    dim3 agrid(N_ / 2, B_);
    aggregate_kernel<<<agrid, 256>>>(out);
}

// round 9
// speedup vs baseline: 2.1714x; 1.4228x over previous
#include <cuda_runtime.h>
#include <cuda_fp16.h>
#include <math_constants.h>
#include <cstdint>

#define B_ 4
#define N_ 20000
#define F_ 256
#define H_ 8
#define D_ 32
#define E_ 320000
#define M_ (B_ * N_)   // 80000 rows in flattened GEMM

// ---------------------------------------------------------------------------
// Scratch
// ---------------------------------------------------------------------------
__device__ __half   g_hp16[(size_t)M_ * F_];        // [B,N,H,D] fp16 (~41MB)
__device__ float    g_asrc[(size_t)M_ * H_];        // [B,N,H]
__device__ float    g_atrg[(size_t)M_ * H_];        // [B,N,H]
__device__ int      g_counts[M_];                   // per (b,n) in-degree
__device__ int      g_offsets[M_];                  // exclusive scan per batch
__device__ int      g_cursor[M_];                   // fill cursors
__device__ int      g_sorted_src[(size_t)B_ * E_];  // CSR payload: src per slot
__device__ int      g_segsum[64];                   // scan phase partials

#define SCAN_SEGS 10
#define SCAN_SEG_LEN 2000
#define SCAN_PER_THR 8

// ---------------------------------------------------------------------------
// helpers
// ---------------------------------------------------------------------------
__device__ __forceinline__ void mma_fp16(float c[4], uint32_t a0, uint32_t a1,
                                         uint32_t a2, uint32_t a3,
                                         uint32_t b0, uint32_t b1) {
    asm volatile(
        "mma.sync.aligned.m16n8k16.row.col.f32.f16.f16.f32 "
        "{%0,%1,%2,%3},{%4,%5,%6,%7},{%8,%9},{%0,%1,%2,%3};"
        : "+f"(c[0]), "+f"(c[1]), "+f"(c[2]), "+f"(c[3])
        : "r"(a0), "r"(a1), "r"(a2), "r"(a3), "r"(b0), "r"(b1));
}

__device__ __forceinline__ float leaky_exp(float x) {
    x = x > 0.f ? x : 0.2f * x;
    return __expf(x);
}

// ---------------------------------------------------------------------------
// 0) init
// ---------------------------------------------------------------------------
__global__ void init_kernel() {
    int i = blockIdx.x * blockDim.x + threadIdx.x;
    if (i < M_) { g_counts[i] = 0; g_cursor[i] = 0; }
}

// ---------------------------------------------------------------------------
// 1) fp16 GEMM (fp32 accum): A[M,256] @ W[256,256]^T -> g_hp16, fused a_src/a_trg.
// ---------------------------------------------------------------------------
#define BK_ 16
#define BKP_ 24
__global__ __launch_bounds__(256) void gemm_fp16_kernel(const float* __restrict__ A,
                                                        const float* __restrict__ W,
                                                        const float* __restrict__ attn_src,
                                                        const float* __restrict__ attn_trg) {
    __shared__ __half As[128][BKP_];
    __shared__ __half Bs[128][BKP_];

    const int tid   = threadIdx.x;
    const int lane  = tid & 31;
    const int wid   = tid >> 5;
    const int warpM = wid >> 2;
    const int warpN = wid & 3;
    const int bm    = blockIdx.x * 128;
    const int bn    = blockIdx.y * 128;

    const int lr = tid >> 2;
    const int lc = (tid & 3) * 4;

    float c[4][4][4];
#pragma unroll
    for (int i = 0; i < 4; i++)
#pragma unroll
        for (int j = 0; j < 4; j++)
#pragma unroll
            for (int q = 0; q < 4; q++) c[i][j][q] = 0.f;

    float4 av0 = *(const float4*)(A + (size_t)(bm + lr) * 256 + lc);
    float4 av1 = *(const float4*)(A + (size_t)(bm + lr + 64) * 256 + lc);
    float4 bv0 = *(const float4*)(W + (size_t)(bn + lr) * 256 + lc);
    float4 bv1 = *(const float4*)(W + (size_t)(bn + lr + 64) * 256 + lc);

    const int r = lane >> 2;
    const int q = lane & 3;

    for (int k0 = 0; k0 < 256; k0 += BK_) {
        *(__half2*)&As[lr][lc]          = __floats2half2_rn(av0.x, av0.y);
        *(__half2*)&As[lr][lc + 2]      = __floats2half2_rn(av0.z, av0.w);
        *(__half2*)&As[lr + 64][lc]     = __floats2half2_rn(av1.x, av1.y);
        *(__half2*)&As[lr + 64][lc + 2] = __floats2half2_rn(av1.z, av1.w);
        *(__half2*)&Bs[lr][lc]          = __floats2half2_rn(bv0.x, bv0.y);
        *(__half2*)&Bs[lr][lc + 2]      = __floats2half2_rn(bv0.z, bv0.w);
        *(__half2*)&Bs[lr + 64][lc]     = __floats2half2_rn(bv1.x, bv1.y);
        *(__half2*)&Bs[lr + 64][lc + 2] = __floats2half2_rn(bv1.z, bv1.w);
        __syncthreads();

        if (k0 + BK_ < 256) {
            av0 = *(const float4*)(A + (size_t)(bm + lr) * 256 + k0 + BK_ + lc);
            av1 = *(const float4*)(A + (size_t)(bm + lr + 64) * 256 + k0 + BK_ + lc);
            bv0 = *(const float4*)(W + (size_t)(bn + lr) * 256 + k0 + BK_ + lc);
            bv1 = *(const float4*)(W + (size_t)(bn + lr + 64) * 256 + k0 + BK_ + lc);
        }

        uint32_t a[4][4], bf[4][2];
#pragma unroll
        for (int i = 0; i < 4; i++) {
            int row = warpM * 64 + i * 16;
            a[i][0] = *(const uint32_t*)&As[row + r][2 * q];
            a[i][1] = *(const uint32_t*)&As[row + r + 8][2 * q];
            a[i][2] = *(const uint32_t*)&As[row + r][2 * q + 8];
            a[i][3] = *(const uint32_t*)&As[row + r + 8][2 * q + 8];
        }
#pragma unroll
        for (int j = 0; j < 4; j++) {
            int col = warpN * 32 + j * 8 + r;
            bf[j][0] = *(const uint32_t*)&Bs[col][2 * q];
            bf[j][1] = *(const uint32_t*)&Bs[col][2 * q + 8];
        }
#pragma unroll
        for (int i = 0; i < 4; i++)
#pragma unroll
            for (int j = 0; j < 4; j++)
                mma_fp16(c[i][j], a[i][0], a[i][1], a[i][2], a[i][3],
                         bf[j][0], bf[j][1]);
        __syncthreads();
    }

    const int head = (bn >> 5) + warpN;

    float ws[8], wt[8];
#pragma unroll
    for (int j = 0; j < 4; j++) {
        int col = head * 32 + j * 8 + 2 * q;
        ws[2 * j + 0] = __ldg(&attn_src[col]);
        ws[2 * j + 1] = __ldg(&attn_src[col + 1]);
        wt[2 * j + 0] = __ldg(&attn_trg[col]);
        wt[2 * j + 1] = __ldg(&attn_trg[col + 1]);
    }

#pragma unroll
    for (int i = 0; i < 4; i++) {
        int m0 = bm + warpM * 64 + i * 16 + r;
        float s0 = 0.f, s1 = 0.f, t0 = 0.f, t1 = 0.f;
#pragma unroll
        for (int j = 0; j < 4; j++) {
            __half* base = g_hp16 + (size_t)m0 * 256 + bn + warpN * 32 + j * 8 + 2 * q;
            *(__half2*)base = __floats2half2_rn(c[i][j][0], c[i][j][1]);
            *(__half2*)(base + 8 * 256) = __floats2half2_rn(c[i][j][2], c[i][j][3]);
            s0 += c[i][j][0] * ws[2 * j] + c[i][j][1] * ws[2 * j + 1];
            s1 += c[i][j][2] * ws[2 * j] + c[i][j][3] * ws[2 * j + 1];
            t0 += c[i][j][0] * wt[2 * j] + c[i][j][1] * wt[2 * j + 1];
            t1 += c[i][j][2] * wt[2 * j] + c[i][j][3] * wt[2 * j + 1];
        }
#pragma unroll
        for (int o = 1; o < 4; o <<= 1) {
            s0 += __shfl_xor_sync(0xffffffffu, s0, o);
            s1 += __shfl_xor_sync(0xffffffffu, s1, o);
            t0 += __shfl_xor_sync(0xffffffffu, t0, o);
            t1 += __shfl_xor_sync(0xffffffffu, t1, o);
        }
        if (q == 0) {
            g_asrc[(size_t)m0 * H_ + head]       = s0;
            g_asrc[(size_t)(m0 + 8) * H_ + head] = s1;
            g_atrg[(size_t)m0 * H_ + head]       = t0;
            g_atrg[(size_t)(m0 + 8) * H_ + head] = t1;
        }
    }
}

// ---------------------------------------------------------------------------
// 2) histogram of targets
// ---------------------------------------------------------------------------
__global__ __launch_bounds__(256) void hist_kernel(const int* __restrict__ ei) {
    int b = blockIdx.y;
    int e = blockIdx.x * 256 + threadIdx.x;
    if (e < E_) {
        int trg = ei[(size_t)b * 2 * E_ + E_ + e];
        atomicAdd(&g_counts[b * N_ + trg], 1);
    }
}

// ---------------------------------------------------------------------------
// 3) scan, 2-phase
// ---------------------------------------------------------------------------
__global__ __launch_bounds__(256) void scan1_kernel() {
    const int seg  = blockIdx.x;
    const int base = seg * SCAN_SEG_LEN;
    int local = 0;
    for (int i = threadIdx.x; i < SCAN_SEG_LEN; i += 256)
        local += g_counts[base + i];
#pragma unroll
    for (int o = 16; o > 0; o >>= 1) local += __shfl_xor_sync(0xffffffffu, local, o);
    __shared__ int warpsum[8];
    if ((threadIdx.x & 31) == 0) warpsum[threadIdx.x >> 5] = local;
    __syncthreads();
    if (threadIdx.x == 0) {
        int s = 0;
#pragma unroll
        for (int w = 0; w < 8; w++) s += warpsum[w];
        g_segsum[seg] = s;
    }
}

__global__ __launch_bounds__(256) void scan3_kernel() {
    const int seg  = blockIdx.x;
    const int base = seg * SCAN_SEG_LEN;
    const int tid  = threadIdx.x;
    __shared__ int sums[256];
    __shared__ int segbase;

    if (tid == 0) {
        int b = seg / SCAN_SEGS;
        int s = 0;
        for (int k = b * SCAN_SEGS; k < seg; k++) s += g_segsum[k];
        segbase = s;
    }

    int vals[SCAN_PER_THR];
    int tb = tid * SCAN_PER_THR;
    int local = 0;
#pragma unroll
    for (int i = 0; i < SCAN_PER_THR; i++) {
        int idx = tb + i;
        vals[i] = (idx < SCAN_SEG_LEN) ? g_counts[base + idx] : 0;
        local += vals[i];
    }
    int v = local;
    int lane = tid & 31, w = tid >> 5;
#pragma unroll
    for (int o = 1; o < 32; o <<= 1) {
        int u = __shfl_up_sync(0xffffffffu, v, o);
        if (lane >= o) v += u;
    }
    __shared__ int wsum[8];
    if (lane == 31) wsum[w] = v;
    __syncthreads();
    if (tid < 8) {
        int u = wsum[tid];
#pragma unroll
        for (int o = 1; o < 8; o <<= 1) {
            int p = __shfl_up_sync(0xffu, u, o);
            if (tid >= o) u += p;
        }
        sums[tid] = u;
    }
    __syncthreads();
    int prefix = v - local + (w > 0 ? sums[w - 1] : 0) + segbase;
#pragma unroll
    for (int i = 0; i < SCAN_PER_THR; i++) {
        int idx = tb + i;
        if (idx < SCAN_SEG_LEN) {
            g_offsets[base + idx] = prefix;
            prefix += vals[i];
        }
    }
}

// ---------------------------------------------------------------------------
// 4) fill CSR buckets (src only)
// ---------------------------------------------------------------------------
__global__ __launch_bounds__(256) void fill_kernel(const int* __restrict__ ei) {
    int b = blockIdx.y;
    int e = blockIdx.x * 256 + threadIdx.x;
    if (e >= E_) return;
    int src = ei[(size_t)b * 2 * E_ + e];
    int trg = ei[(size_t)b * 2 * E_ + E_ + e];
    int pos = g_offsets[b * N_ + trg] + atomicAdd(&g_cursor[b * N_ + trg], 1);
    g_sorted_src[(size_t)b * E_ + pos] = src;
}

// ---------------------------------------------------------------------------
// 5) gather-aggregate: ONE warp per node, all 8 heads.
//    Lane l owns half4 row slices at halves [4l,4l+4) (head l>>3) and
//    [128+4l,128+4l+4) (head 4+(l>>3)). Per edge: 2 coalesced LDG.64.
//    Weights: lane e computes all 8 heads of edge e into per-warp smem,
//    interleaved so (h, h+4) are adjacent -> single LDS.64 broadcast.
// ---------------------------------------------------------------------------
__global__ __launch_bounds__(256) void aggregate_kernel(float* __restrict__ out) {
    const int tid  = threadIdx.x;
    const int wid  = tid >> 5;               // 0..7, one node per warp
    const int lane = tid & 31;
    const int n    = blockIdx.x * 8 + wid;
    const int b    = blockIdx.y;

    __shared__ int   s_src[8][32];
    __shared__ float s_w[8][32][8];          // [warp][edge][h'] h'=(h&3)*2+(h>>2)

    const int off = g_offsets[b * N_ + n];
    const int deg = g_counts[b * N_ + n];

    // a_trg for this node (broadcast 32B load)
    const float4 at0 = *(const float4*)(g_atrg + (size_t)(b * N_ + n) * H_);
    const float4 at1 = *(const float4*)(g_atrg + (size_t)(b * N_ + n) * H_ + 4);

    const int*    srcs = g_sorted_src + (size_t)b * E_ + off;
    const float*  asb  = g_asrc + (size_t)b * N_ * H_;
    const __half* hpb  = g_hp16 + (size_t)b * N_ * 256;

    const int hgrp = lane >> 3;              // head group 0..3
    const int dofs = 4 * lane;               // half offset of first slice

    float4 acc0 = make_float4(0.f, 0.f, 0.f, 0.f);
    float4 acc1 = make_float4(0.f, 0.f, 0.f, 0.f);
    float  den0 = 0.f, den1 = 0.f;

    for (int c0 = 0; c0 < deg; c0 += 32) {
        const int cnt = min(32, deg - c0);
        if (lane < cnt) {
            int src = __ldg(srcs + c0 + lane);
            s_src[wid][lane] = src;
            const float4 a0 = *(const float4*)(asb + (size_t)src * H_);
            const float4 a1 = *(const float4*)(asb + (size_t)src * H_ + 4);
            s_w[wid][lane][0] = leaky_exp(a0.x + at0.x);   // h=0
            s_w[wid][lane][2] = leaky_exp(a0.y + at0.y);   // h=1
            s_w[wid][lane][4] = leaky_exp(a0.z + at0.z);   // h=2
            s_w[wid][lane][6] = leaky_exp(a0.w + at0.w);   // h=3
            s_w[wid][lane][1] = leaky_exp(a1.x + at1.x);   // h=4
            s_w[wid][lane][3] = leaky_exp(a1.y + at1.y);   // h=5
            s_w[wid][lane][5] = leaky_exp(a1.z + at1.z);   // h=6
            s_w[wid][lane][7] = leaky_exp(a1.w + at1.w);   // h=7
        }
        __syncwarp();

        int j = 0;
        for (; j + 2 <= cnt; j += 2) {
            const int sA = s_src[wid][j];
            const int sB = s_src[wid][j + 1];
            const float2 wA = *(const float2*)&s_w[wid][j][2 * hgrp];
            const float2 wB = *(const float2*)&s_w[wid][j + 1][2 * hgrp];
            const __half* rA = hpb + (size_t)sA * 256 + dofs;
            const __half* rB = hpb + (size_t)sB * 256 + dofs;
            uint2 pA0 = __ldg((const uint2*)rA);
            uint2 pA1 = __ldg((const uint2*)(rA + 128));
            uint2 pB0 = __ldg((const uint2*)rB);
            uint2 pB1 = __ldg((const uint2*)(rB + 128));
            den0 += wA.x + wB.x;
            den1 += wA.y + wB.y;
            float2 a0 = __half22float2(*(__half2*)&pA0.x);
            float2 a1 = __half22float2(*(__half2*)&pA0.y);
            float2 a2 = __half22float2(*(__half2*)&pA1.x);
            float2 a3 = __half22float2(*(__half2*)&pA1.y);
            acc0.x = fmaf(wA.x, a0.x, acc0.x); acc0.y = fmaf(wA.x, a0.y, acc0.y);
            acc0.z = fmaf(wA.x, a1.x, acc0.z); acc0.w = fmaf(wA.x, a1.y, acc0.w);
            acc1.x = fmaf(wA.y, a2.x, acc1.x); acc1.y = fmaf(wA.y, a2.y, acc1.y);
            acc1.z = fmaf(wA.y, a3.x, acc1.z); acc1.w = fmaf(wA.y, a3.y, acc1.w);
            float2 b0 = __half22float2(*(__half2*)&pB0.x);
            float2 b1 = __half22float2(*(__half2*)&pB0.y);
            float2 b2 = __half22float2(*(__half2*)&pB1.x);
            float2 b3 = __half22float2(*(__half2*)&pB1.y);
            acc0.x = fmaf(wB.x, b0.x, acc0.x); acc0.y = fmaf(wB.x, b0.y, acc0.y);
            acc0.z = fmaf(wB.x, b1.x, acc0.z); acc0.w = fmaf(wB.x, b1.y, acc0.w);
            acc1.x = fmaf(wB.y, b2.x, acc1.x); acc1.y = fmaf(wB.y, b2.y, acc1.y);
            acc1.z = fmaf(wB.y, b3.x, acc1.z); acc1.w = fmaf(wB.y, b3.y, acc1.w);
        }
        if (j < cnt) {
            const int s = s_src[wid][j];
            const float2 w = *(const float2*)&s_w[wid][j][2 * hgrp];
            const __half* rr = hpb + (size_t)s * 256 + dofs;
            uint2 p0 = __ldg((const uint2*)rr);
            uint2 p1 = __ldg((const uint2*)(rr + 128));
            den0 += w.x; den1 += w.y;
            float2 a0 = __half22float2(*(__half2*)&p0.x);
            float2 a1 = __half22float2(*(__half2*)&p0.y);
            float2 a2 = __half22float2(*(__half2*)&p1.x);
            float2 a3 = __half22float2(*(__half2*)&p1.y);
            acc0.x = fmaf(w.x, a0.x, acc0.x); acc0.y = fmaf(w.x, a0.y, acc0.y);
            acc0.z = fmaf(w.x, a1.x, acc0.z); acc0.w = fmaf(w.x, a1.y, acc0.w);
            acc1.x = fmaf(w.y, a2.x, acc1.x); acc1.y = fmaf(w.y, a2.y, acc1.y);
            acc1.z = fmaf(w.y, a3.x, acc1.z); acc1.w = fmaf(w.y, a3.y, acc1.w);
        }
        __syncwarp();
    }

    const float i0 = 1.f / (den0 + 1e-16f);
    const float i1 = 1.f / (den1 + 1e-16f);
    const int d0 = 4 * (lane & 7);
    float4* o0 = (float4*)(out + (((size_t)b * H_ + hgrp) * N_ + n) * D_ + d0);
    float4* o1 = (float4*)(out + (((size_t)b * H_ + hgrp + 4) * N_ + n) * D_ + d0);
    *o0 = make_float4(acc0.x * i0, acc0.y * i0, acc0.z * i0, acc0.w * i0);
    *o1 = make_float4(acc1.x * i1, acc1.y * i1, acc1.z * i1, acc1.w * i1);
}

// ---------------------------------------------------------------------------
// kernel_launch — fork edge-prep onto a side stream, overlap with GEMM.
// ---------------------------------------------------------------------------
extern "C" void kernel_launch(void* const* d_in, const int* in_sizes, int n_in,
                              void* d_out, int out_size) {
    const float* h        = (const float*)d_in[0];
    const int*   ei       = (const int*)d_in[1];
    const float* W        = (const float*)d_in[2];
    const float* attn_src = (const float*)d_in[3];
    const float* attn_trg = (const float*)d_in[4];
    float*       out      = (float*)d_out;

    static cudaStream_t s_side = nullptr;
    static cudaEvent_t  ev_fork = nullptr, ev_join = nullptr;
    if (s_side == nullptr) {
        cudaStreamCreateWithFlags(&s_side, cudaStreamNonBlocking);
        cudaEventCreateWithFlags(&ev_fork, cudaEventDisableTiming);
        cudaEventCreateWithFlags(&ev_join, cudaEventDisableTiming);
    }

    // fork
    cudaEventRecord(ev_fork, 0);
    cudaStreamWaitEvent(s_side, ev_fork, 0);

    // side stream: edge prep (independent of GEMM)
    dim3 egrid((E_ + 255) / 256, B_);
    init_kernel<<<(M_ + 255) / 256, 256, 0, s_side>>>();
    hist_kernel<<<egrid, 256, 0, s_side>>>(ei);
    scan1_kernel<<<B_ * SCAN_SEGS, 256, 0, s_side>>>();
    scan3_kernel<<<B_ * SCAN_SEGS, 256, 0, s_side>>>();
    fill_kernel<<<egrid, 256, 0, s_side>>>(ei);
    cudaEventRecord(ev_join, s_side);

    // main stream: GEMM (+ fused projections)
    dim3 ggrid(M_ / 128, 256 / 128);
    gemm_fp16_kernel<<<ggrid, 256>>>(h, W, attn_src, attn_trg);

    // join, then aggregate
    cudaStreamWaitEvent(0, ev_join, 0);
    dim3 agrid(N_ / 8, B_);
    aggregate_kernel<<<agrid, 256>>>(out);
}

// round 11
// speedup vs baseline: 2.2253x; 1.0248x over previous
#include <cuda_runtime.h>
#include <cuda_fp16.h>
#include <math_constants.h>
#include <cstdint>

#define B_ 4
#define N_ 20000
#define F_ 256
#define H_ 8
#define D_ 32
#define E_ 320000
#define M_ (B_ * N_)   // 80000 rows in flattened GEMM

// ---------------------------------------------------------------------------
// Scratch
// ---------------------------------------------------------------------------
__device__ __half   g_hp16[(size_t)M_ * F_];        // [B,N,H,D] fp16 (~41MB)
__device__ float    g_asrc[(size_t)M_ * H_];        // [B,N,H]
__device__ float    g_atrg[(size_t)M_ * H_];        // [B,N,H]
__device__ int      g_counts[M_];                   // per (b,n) in-degree
__device__ int      g_offsets[M_];                  // scan; fill bumps to END
__device__ int      g_sorted_src[(size_t)B_ * E_];  // CSR payload: src per slot
__device__ int      g_segsum[64];                   // scan phase partials

#define SCAN_SEGS 10
#define SCAN_SEG_LEN 2000
#define SCAN_PER_THR 8

// ---------------------------------------------------------------------------
// helpers
// ---------------------------------------------------------------------------
__device__ __forceinline__ void mma_fp16(float c[4], uint32_t a0, uint32_t a1,
                                         uint32_t a2, uint32_t a3,
                                         uint32_t b0, uint32_t b1) {
    asm volatile(
        "mma.sync.aligned.m16n8k16.row.col.f32.f16.f16.f32 "
        "{%0,%1,%2,%3},{%4,%5,%6,%7},{%8,%9},{%0,%1,%2,%3};"
        : "+f"(c[0]), "+f"(c[1]), "+f"(c[2]), "+f"(c[3])
        : "r"(a0), "r"(a1), "r"(a2), "r"(a3), "r"(b0), "r"(b1));
}

__device__ __forceinline__ float leaky_exp(float x) {
    x = x > 0.f ? x : 0.2f * x;
    return __expf(x);
}

// ---------------------------------------------------------------------------
// 0) init: zero counts only (cursor eliminated)
// ---------------------------------------------------------------------------
__global__ void init_kernel() {
    int i = blockIdx.x * blockDim.x + threadIdx.x;
    if (i < M_) g_counts[i] = 0;
}

// ---------------------------------------------------------------------------
// 1) fp16 GEMM (fp32 accum): A[M,256] @ W[256,256]^T -> g_hp16, fused a_src/a_trg.
// ---------------------------------------------------------------------------
#define BK_ 16
#define BKP_ 24
__global__ __launch_bounds__(256) void gemm_fp16_kernel(const float* __restrict__ A,
                                                        const float* __restrict__ W,
                                                        const float* __restrict__ attn_src,
                                                        const float* __restrict__ attn_trg) {
    __shared__ __half As[128][BKP_];
    __shared__ __half Bs[128][BKP_];

    const int tid   = threadIdx.x;
    const int lane  = tid & 31;
    const int wid   = tid >> 5;
    const int warpM = wid >> 2;
    const int warpN = wid & 3;
    const int bm    = blockIdx.x * 128;
    const int bn    = blockIdx.y * 128;

    const int lr = tid >> 2;
    const int lc = (tid & 3) * 4;

    float c[4][4][4];
#pragma unroll
    for (int i = 0; i < 4; i++)
#pragma unroll
        for (int j = 0; j < 4; j++)
#pragma unroll
            for (int q = 0; q < 4; q++) c[i][j][q] = 0.f;

    float4 av0 = *(const float4*)(A + (size_t)(bm + lr) * 256 + lc);
    float4 av1 = *(const float4*)(A + (size_t)(bm + lr + 64) * 256 + lc);
    float4 bv0 = *(const float4*)(W + (size_t)(bn + lr) * 256 + lc);
    float4 bv1 = *(const float4*)(W + (size_t)(bn + lr + 64) * 256 + lc);

    const int r = lane >> 2;
    const int q = lane & 3;

    for (int k0 = 0; k0 < 256; k0 += BK_) {
        *(__half2*)&As[lr][lc]          = __floats2half2_rn(av0.x, av0.y);
        *(__half2*)&As[lr][lc + 2]      = __floats2half2_rn(av0.z, av0.w);
        *(__half2*)&As[lr + 64][lc]     = __floats2half2_rn(av1.x, av1.y);
        *(__half2*)&As[lr + 64][lc + 2] = __floats2half2_rn(av1.z, av1.w);
        *(__half2*)&Bs[lr][lc]          = __floats2half2_rn(bv0.x, bv0.y);
        *(__half2*)&Bs[lr][lc + 2]      = __floats2half2_rn(bv0.z, bv0.w);
        *(__half2*)&Bs[lr + 64][lc]     = __floats2half2_rn(bv1.x, bv1.y);
        *(__half2*)&Bs[lr + 64][lc + 2] = __floats2half2_rn(bv1.z, bv1.w);
        __syncthreads();

        if (k0 + BK_ < 256) {
            av0 = *(const float4*)(A + (size_t)(bm + lr) * 256 + k0 + BK_ + lc);
            av1 = *(const float4*)(A + (size_t)(bm + lr + 64) * 256 + k0 + BK_ + lc);
            bv0 = *(const float4*)(W + (size_t)(bn + lr) * 256 + k0 + BK_ + lc);
            bv1 = *(const float4*)(W + (size_t)(bn + lr + 64) * 256 + k0 + BK_ + lc);
        }

        uint32_t a[4][4], bf[4][2];
#pragma unroll
        for (int i = 0; i < 4; i++) {
            int row = warpM * 64 + i * 16;
            a[i][0] = *(const uint32_t*)&As[row + r][2 * q];
            a[i][1] = *(const uint32_t*)&As[row + r + 8][2 * q];
            a[i][2] = *(const uint32_t*)&As[row + r][2 * q + 8];
            a[i][3] = *(const uint32_t*)&As[row + r + 8][2 * q + 8];
        }
#pragma unroll
        for (int j = 0; j < 4; j++) {
            int col = warpN * 32 + j * 8 + r;
            bf[j][0] = *(const uint32_t*)&Bs[col][2 * q];
            bf[j][1] = *(const uint32_t*)&Bs[col][2 * q + 8];
        }
#pragma unroll
        for (int i = 0; i < 4; i++)
#pragma unroll
            for (int j = 0; j < 4; j++)
                mma_fp16(c[i][j], a[i][0], a[i][1], a[i][2], a[i][3],
                         bf[j][0], bf[j][1]);
        __syncthreads();
    }

    const int head = (bn >> 5) + warpN;

    float ws[8], wt[8];
#pragma unroll
    for (int j = 0; j < 4; j++) {
        int col = head * 32 + j * 8 + 2 * q;
        ws[2 * j + 0] = __ldg(&attn_src[col]);
        ws[2 * j + 1] = __ldg(&attn_src[col + 1]);
        wt[2 * j + 0] = __ldg(&attn_trg[col]);
        wt[2 * j + 1] = __ldg(&attn_trg[col + 1]);
    }

#pragma unroll
    for (int i = 0; i < 4; i++) {
        int m0 = bm + warpM * 64 + i * 16 + r;
        float s0 = 0.f, s1 = 0.f, t0 = 0.f, t1 = 0.f;
#pragma unroll
        for (int j = 0; j < 4; j++) {
            __half* base = g_hp16 + (size_t)m0 * 256 + bn + warpN * 32 + j * 8 + 2 * q;
            *(__half2*)base = __floats2half2_rn(c[i][j][0], c[i][j][1]);
            *(__half2*)(base + 8 * 256) = __floats2half2_rn(c[i][j][2], c[i][j][3]);
            s0 += c[i][j][0] * ws[2 * j] + c[i][j][1] * ws[2 * j + 1];
            s1 += c[i][j][2] * ws[2 * j] + c[i][j][3] * ws[2 * j + 1];
            t0 += c[i][j][0] * wt[2 * j] + c[i][j][1] * wt[2 * j + 1];
            t1 += c[i][j][2] * wt[2 * j] + c[i][j][3] * wt[2 * j + 1];
        }
#pragma unroll
        for (int o = 1; o < 4; o <<= 1) {
            s0 += __shfl_xor_sync(0xffffffffu, s0, o);
            s1 += __shfl_xor_sync(0xffffffffu, s1, o);
            t0 += __shfl_xor_sync(0xffffffffu, t0, o);
            t1 += __shfl_xor_sync(0xffffffffu, t1, o);
        }
        if (q == 0) {
            g_asrc[(size_t)m0 * H_ + head]       = s0;
            g_asrc[(size_t)(m0 + 8) * H_ + head] = s1;
            g_atrg[(size_t)m0 * H_ + head]       = t0;
            g_atrg[(size_t)(m0 + 8) * H_ + head] = t1;
        }
    }
}

// ---------------------------------------------------------------------------
// 2) histogram of targets
// ---------------------------------------------------------------------------
__global__ __launch_bounds__(256) void hist_kernel(const int* __restrict__ ei) {
    int b = blockIdx.y;
    int e = blockIdx.x * 256 + threadIdx.x;
    if (e < E_) {
        int trg = ei[(size_t)b * 2 * E_ + E_ + e];
        atomicAdd(&g_counts[b * N_ + trg], 1);
    }
}

// ---------------------------------------------------------------------------
// 3) scan, 2-phase
// ---------------------------------------------------------------------------
__global__ __launch_bounds__(256) void scan1_kernel() {
    const int seg  = blockIdx.x;
    const int base = seg * SCAN_SEG_LEN;
    int local = 0;
    for (int i = threadIdx.x; i < SCAN_SEG_LEN; i += 256)
        local += g_counts[base + i];
#pragma unroll
    for (int o = 16; o > 0; o >>= 1) local += __shfl_xor_sync(0xffffffffu, local, o);
    __shared__ int warpsum[8];
    if ((threadIdx.x & 31) == 0) warpsum[threadIdx.x >> 5] = local;
    __syncthreads();
    if (threadIdx.x == 0) {
        int s = 0;
#pragma unroll
        for (int w = 0; w < 8; w++) s += warpsum[w];
        g_segsum[seg] = s;
    }
}

__global__ __launch_bounds__(256) void scan3_kernel() {
    const int seg  = blockIdx.x;
    const int base = seg * SCAN_SEG_LEN;
    const int tid  = threadIdx.x;
    __shared__ int sums[256];
    __shared__ int segbase;

    if (tid == 0) {
        int b = seg / SCAN_SEGS;
        int s = 0;
        for (int k = b * SCAN_SEGS; k < seg; k++) s += g_segsum[k];
        segbase = s;
    }

    int vals[SCAN_PER_THR];
    int tb = tid * SCAN_PER_THR;
    int local = 0;
#pragma unroll
    for (int i = 0; i < SCAN_PER_THR; i++) {
        int idx = tb + i;
        vals[i] = (idx < SCAN_SEG_LEN) ? g_counts[base + idx] : 0;
        local += vals[i];
    }
    int v = local;
    int lane = tid & 31, w = tid >> 5;
#pragma unroll
    for (int o = 1; o < 32; o <<= 1) {
        int u = __shfl_up_sync(0xffffffffu, v, o);
        if (lane >= o) v += u;
    }
    __shared__ int wsum[8];
    if (lane == 31) wsum[w] = v;
    __syncthreads();
    if (tid < 8) {
        int u = wsum[tid];
#pragma unroll
        for (int o = 1; o < 8; o <<= 1) {
            int p = __shfl_up_sync(0xffu, u, o);
            if (tid >= o) u += p;
        }
        sums[tid] = u;
    }
    __syncthreads();
    int prefix = v - local + (w > 0 ? sums[w - 1] : 0) + segbase;
#pragma unroll
    for (int i = 0; i < SCAN_PER_THR; i++) {
        int idx = tb + i;
        if (idx < SCAN_SEG_LEN) {
            g_offsets[base + idx] = prefix;
            prefix += vals[i];
        }
    }
}

// ---------------------------------------------------------------------------
// 4) fill CSR buckets: atomically bump g_offsets itself (post-fill it = END).
//    Safe under graph replay: scan rewrites g_offsets fresh every run.
// ---------------------------------------------------------------------------
__global__ __launch_bounds__(256) void fill_kernel(const int* __restrict__ ei) {
    int b = blockIdx.y;
    int e = blockIdx.x * 256 + threadIdx.x;
    if (e >= E_) return;
    int src = ei[(size_t)b * 2 * E_ + e];
    int trg = ei[(size_t)b * 2 * E_ + E_ + e];
    int pos = atomicAdd(&g_offsets[b * N_ + trg], 1);
    g_sorted_src[(size_t)b * E_ + pos] = src;
}

// ---------------------------------------------------------------------------
// 5) gather-aggregate: ONE warp per node, all 8 heads, unroll-4 (8 LDG.64/lane).
//    start = offsets[n] - counts[n]  (offsets holds END after fill).
// ---------------------------------------------------------------------------
__global__ __launch_bounds__(256) void aggregate_kernel(float* __restrict__ out) {
    const int tid  = threadIdx.x;
    const int wid  = tid >> 5;               // 0..7, one node per warp
    const int lane = tid & 31;
    const int n    = blockIdx.x * 8 + wid;
    const int b    = blockIdx.y;

    __shared__ int   s_src[8][32];
    __shared__ float s_w[8][32][8];          // [warp][edge][h'] h'=(h&3)*2+(h>>2)

    const int deg = g_counts[b * N_ + n];
    const int off = g_offsets[b * N_ + n] - deg;   // offsets = end after fill

    const float4 at0 = *(const float4*)(g_atrg + (size_t)(b * N_ + n) * H_);
    const float4 at1 = *(const float4*)(g_atrg + (size_t)(b * N_ + n) * H_ + 4);

    const int*    srcs = g_sorted_src + (size_t)b * E_ + off;
    const float*  asb  = g_asrc + (size_t)b * N_ * H_;
    const __half* hpb  = g_hp16 + (size_t)b * N_ * 256;

    const int hgrp = lane >> 3;              // head group 0..3
    const int dofs = 4 * lane;               // half offset of first slice

    float4 acc0 = make_float4(0.f, 0.f, 0.f, 0.f);
    float4 acc1 = make_float4(0.f, 0.f, 0.f, 0.f);
    float  den0 = 0.f, den1 = 0.f;

    for (int c0 = 0; c0 < deg; c0 += 32) {
        const int cnt = min(32, deg - c0);
        if (lane < cnt) {
            int src = __ldg(srcs + c0 + lane);
            s_src[wid][lane] = src;
            const float4 a0 = *(const float4*)(asb + (size_t)src * H_);
            const float4 a1 = *(const float4*)(asb + (size_t)src * H_ + 4);
            s_w[wid][lane][0] = leaky_exp(a0.x + at0.x);
            s_w[wid][lane][2] = leaky_exp(a0.y + at0.y);
            s_w[wid][lane][4] = leaky_exp(a0.z + at0.z);
            s_w[wid][lane][6] = leaky_exp(a0.w + at0.w);
            s_w[wid][lane][1] = leaky_exp(a1.x + at1.x);
            s_w[wid][lane][3] = leaky_exp(a1.y + at1.y);
            s_w[wid][lane][5] = leaky_exp(a1.z + at1.z);
            s_w[wid][lane][7] = leaky_exp(a1.w + at1.w);
        }
        __syncwarp();

        int j = 0;
        for (; j + 4 <= cnt; j += 4) {
            int   sA = s_src[wid][j],     sB = s_src[wid][j + 1];
            int   sC = s_src[wid][j + 2], sD = s_src[wid][j + 3];
            float2 wA = *(const float2*)&s_w[wid][j][2 * hgrp];
            float2 wB = *(const float2*)&s_w[wid][j + 1][2 * hgrp];
            float2 wC = *(const float2*)&s_w[wid][j + 2][2 * hgrp];
            float2 wD = *(const float2*)&s_w[wid][j + 3][2 * hgrp];
            const __half* rA = hpb + (size_t)sA * 256 + dofs;
            const __half* rB = hpb + (size_t)sB * 256 + dofs;
            const __half* rC = hpb + (size_t)sC * 256 + dofs;
            const __half* rD = hpb + (size_t)sD * 256 + dofs;
            uint2 pA0 = __ldg((const uint2*)rA);
            uint2 pA1 = __ldg((const uint2*)(rA + 128));
            uint2 pB0 = __ldg((const uint2*)rB);
            uint2 pB1 = __ldg((const uint2*)(rB + 128));
            uint2 pC0 = __ldg((const uint2*)rC);
            uint2 pC1 = __ldg((const uint2*)(rC + 128));
            uint2 pD0 = __ldg((const uint2*)rD);
            uint2 pD1 = __ldg((const uint2*)(rD + 128));
            den0 += (wA.x + wB.x) + (wC.x + wD.x);
            den1 += (wA.y + wB.y) + (wC.y + wD.y);
            float2 v0, v1, v2, v3;
            v0 = __half22float2(*(__half2*)&pA0.x); v1 = __half22float2(*(__half2*)&pA0.y);
            v2 = __half22float2(*(__half2*)&pA1.x); v3 = __half22float2(*(__half2*)&pA1.y);
            acc0.x = fmaf(wA.x, v0.x, acc0.x); acc0.y = fmaf(wA.x, v0.y, acc0.y);
            acc0.z = fmaf(wA.x, v1.x, acc0.z); acc0.w = fmaf(wA.x, v1.y, acc0.w);
            acc1.x = fmaf(wA.y, v2.x, acc1.x); acc1.y = fmaf(wA.y, v2.y, acc1.y);
            acc1.z = fmaf(wA.y, v3.x, acc1.z); acc1.w = fmaf(wA.y, v3.y, acc1.w);
            v0 = __half22float2(*(__half2*)&pB0.x); v1 = __half22float2(*(__half2*)&pB0.y);
            v2 = __half22float2(*(__half2*)&pB1.x); v3 = __half22float2(*(__half2*)&pB1.y);
            acc0.x = fmaf(wB.x, v0.x, acc0.x); acc0.y = fmaf(wB.x, v0.y, acc0.y);
            acc0.z = fmaf(wB.x, v1.x, acc0.z); acc0.w = fmaf(wB.x, v1.y, acc0.w);
            acc1.x = fmaf(wB.y, v2.x, acc1.x); acc1.y = fmaf(wB.y, v2.y, acc1.y);
            acc1.z = fmaf(wB.y, v3.x, acc1.z); acc1.w = fmaf(wB.y, v3.y, acc1.w);
            v0 = __half22float2(*(__half2*)&pC0.x); v1 = __half22float2(*(__half2*)&pC0.y);
            v2 = __half22float2(*(__half2*)&pC1.x); v3 = __half22float2(*(__half2*)&pC1.y);
            acc0.x = fmaf(wC.x, v0.x, acc0.x); acc0.y = fmaf(wC.x, v0.y, acc0.y);
            acc0.z = fmaf(wC.x, v1.x, acc0.z); acc0.w = fmaf(wC.x, v1.y, acc0.w);
            acc1.x = fmaf(wC.y, v2.x, acc1.x); acc1.y = fmaf(wC.y, v2.y, acc1.y);
            acc1.z = fmaf(wC.y, v3.x, acc1.z); acc1.w = fmaf(wC.y, v3.y, acc1.w);
            v0 = __half22float2(*(__half2*)&pD0.x); v1 = __half22float2(*(__half2*)&pD0.y);
            v2 = __half22float2(*(__half2*)&pD1.x); v3 = __half22float2(*(__half2*)&pD1.y);
            acc0.x = fmaf(wD.x, v0.x, acc0.x); acc0.y = fmaf(wD.x, v0.y, acc0.y);
            acc0.z = fmaf(wD.x, v1.x, acc0.z); acc0.w = fmaf(wD.x, v1.y, acc0.w);
            acc1.x = fmaf(wD.y, v2.x, acc1.x); acc1.y = fmaf(wD.y, v2.y, acc1.y);
            acc1.z = fmaf(wD.y, v3.x, acc1.z); acc1.w = fmaf(wD.y, v3.y, acc1.w);
        }
        for (; j < cnt; j++) {
            const int s = s_src[wid][j];
            const float2 w = *(const float2*)&s_w[wid][j][2 * hgrp];
            const __half* rr = hpb + (size_t)s * 256 + dofs;
            uint2 p0 = __ldg((const uint2*)rr);
            uint2 p1 = __ldg((const uint2*)(rr + 128));
            den0 += w.x; den1 += w.y;
            float2 a0 = __half22float2(*(__half2*)&p0.x);
            float2 a1 = __half22float2(*(__half2*)&p0.y);
            float2 a2 = __half22float2(*(__half2*)&p1.x);
            float2 a3 = __half22float2(*(__half2*)&p1.y);
            acc0.x = fmaf(w.x, a0.x, acc0.x); acc0.y = fmaf(w.x, a0.y, acc0.y);
            acc0.z = fmaf(w.x, a1.x, acc0.z); acc0.w = fmaf(w.x, a1.y, acc0.w);
            acc1.x = fmaf(w.y, a2.x, acc1.x); acc1.y = fmaf(w.y, a2.y, acc1.y);
            acc1.z = fmaf(w.y, a3.x, acc1.z); acc1.w = fmaf(w.y, a3.y, acc1.w);
        }
        __syncwarp();
    }

    const float i0 = 1.f / (den0 + 1e-16f);
    const float i1 = 1.f / (den1 + 1e-16f);
    const int d0 = 4 * (lane & 7);
    float4* o0 = (float4*)(out + (((size_t)b * H_ + hgrp) * N_ + n) * D_ + d0);
    float4* o1 = (float4*)(out + (((size_t)b * H_ + hgrp + 4) * N_ + n) * D_ + d0);
    *o0 = make_float4(acc0.x * i0, acc0.y * i0, acc0.z * i0, acc0.w * i0);
    *o1 = make_float4(acc1.x * i1, acc1.y * i1, acc1.z * i1, acc1.w * i1);
}

// ---------------------------------------------------------------------------
// kernel_launch — fork edge-prep onto a side stream, overlap with GEMM.
// ---------------------------------------------------------------------------
extern "C" void kernel_launch(void* const* d_in, const int* in_sizes, int n_in,
                              void* d_out, int out_size) {
    const float* h        = (const float*)d_in[0];
    const int*   ei       = (const int*)d_in[1];
    const float* W        = (const float*)d_in[2];
    const float* attn_src = (const float*)d_in[3];
    const float* attn_trg = (const float*)d_in[4];
    float*       out      = (float*)d_out;

    static cudaStream_t s_side = nullptr;
    static cudaEvent_t  ev_fork = nullptr, ev_join = nullptr;
    if (s_side == nullptr) {
        cudaStreamCreateWithFlags(&s_side, cudaStreamNonBlocking);
        cudaEventCreateWithFlags(&ev_fork, cudaEventDisableTiming);
        cudaEventCreateWithFlags(&ev_join, cudaEventDisableTiming);
    }

    // fork
    cudaEventRecord(ev_fork, 0);
    cudaStreamWaitEvent(s_side, ev_fork, 0);

    // side stream: edge prep (independent of GEMM)
    dim3 egrid((E_ + 255) / 256, B_);
    init_kernel<<<(M_ + 255) / 256, 256, 0, s_side>>>();
    hist_kernel<<<egrid, 256, 0, s_side>>>(ei);
    scan1_kernel<<<B_ * SCAN_SEGS, 256, 0, s_side>>>();
    scan3_kernel<<<B_ * SCAN_SEGS, 256, 0, s_side>>>();
    fill_kernel<<<egrid, 256, 0, s_side>>>(ei);
    cudaEventRecord(ev_join, s_side);

    // main stream: GEMM (+ fused projections)
    dim3 ggrid(M_ / 128, 256 / 128);
    gemm_fp16_kernel<<<ggrid, 256>>>(h, W, attn_src, attn_trg);

    // join, then aggregate
    cudaStreamWaitEvent(0, ev_join, 0);
    dim3 agrid(N_ / 8, B_);
    aggregate_kernel<<<agrid, 256>>>(out);
}